// round 1
// baseline (speedup 1.0000x reference)
#include <cuda_runtime.h>

#define N_NODES 50000
#define K_NBR   16
#define N_EDGES 200000
#define HID     128
#define NHEAD   4
#define FEAT    160
#define CTX     17

// ---------------- scratch (device globals: no allocation allowed) ----------------
__device__ float g_feats[N_NODES * FEAT];
__device__ float g_xa[N_NODES * HID];
__device__ float g_xb[N_NODES * HID];
__device__ float g_qkv[N_NODES * 3 * HID];
__device__ float g_o[N_NODES * HID];
__device__ int   g_has[N_NODES];
__device__ float g_h1[N_EDGES * HID];
__device__ float g_h2[N_EDGES * 64];

// ---------------- node feature encoding: feats = [type(64), cat0(32), cat1(32), relu(deg)(32)] ----
__global__ void encode_kernel(const int* __restrict__ type_idx,
                              const int* __restrict__ cat_idx,
                              const float* __restrict__ log_deg,
                              const float* __restrict__ type_embed,
                              const float* __restrict__ cat_embed0,
                              const float* __restrict__ cat_embed1,
                              const float* __restrict__ deg_W,
                              const float* __restrict__ deg_b,
                              float* __restrict__ feats)
{
    int i = blockIdx.x * blockDim.x + threadIdx.x;
    if (i >= N_NODES * FEAT) return;
    int n = i / FEAT, j = i - n * FEAT;
    float v;
    if (j < 64)        v = type_embed[type_idx[n] * 64 + j];
    else if (j < 96)   v = cat_embed0[cat_idx[2 * n] * 32 + (j - 64)];
    else if (j < 128)  v = cat_embed1[cat_idx[2 * n + 1] * 32 + (j - 96)];
    else {
        int jj = j - 128;
        v = fmaxf(log_deg[n] * deg_W[jj] + deg_b[jj], 0.f);
    }
    feats[i] = v;
}

__global__ void hasnbr_kernel(const int* __restrict__ nbr_mask, int* __restrict__ has)
{
    int n = blockIdx.x * blockDim.x + threadIdx.x;
    if (n >= N_NODES) return;
    int a = 0;
#pragma unroll
    for (int j = 0; j < K_NBR; j++) a |= nbr_mask[n * K_NBR + j];
    has[n] = a ? 1 : 0;
}

// ---------------- generic tiled GEMM: out = A[rows,KDIM] @ W[KDIM,ldw] + bias ----------------
// MODE 0: none; 1: relu; 2: relu(where(fbmask, val, fbx))
template <int KDIM, int COLS, int MODE>
__global__ void gemm_kernel(const float* __restrict__ A,
                            const float* __restrict__ W, int ldw,
                            const float* __restrict__ bias,
                            float* __restrict__ out, int ldo,
                            int rows,
                            const float* __restrict__ fbx,
                            const int* __restrict__ fbmask)
{
    static_assert(KDIM % 4 == 0, "KDIM must be multiple of 4");
    constexpr int CG = COLS / 4;      // column groups (each thread: 4 cols)
    constexpr int RT = 1024 / CG;     // rows per tile (32 for COLS=128, 64 for COLS=64)

    __shared__ __align__(16) float As[RT][KDIM];
    int t = threadIdx.x;
    int row0 = blockIdx.x * RT;
    int colbase = blockIdx.y * COLS;

    for (int idx = t; idx < RT * KDIM; idx += 256) {
        int r = idx / KDIM, k = idx - r * KDIM;
        int gr = row0 + r;
        As[r][k] = (gr < rows) ? A[(size_t)gr * KDIM + k] : 0.f;
    }
    __syncthreads();

    int cg = t % CG, rg = t / CG;
    int col = colbase + cg * 4;
    float acc[4][4] = {};

#pragma unroll 1
    for (int k = 0; k < KDIM; k += 4) {
        float4 w0 = *reinterpret_cast<const float4*>(&W[(size_t)(k + 0) * ldw + col]);
        float4 w1 = *reinterpret_cast<const float4*>(&W[(size_t)(k + 1) * ldw + col]);
        float4 w2 = *reinterpret_cast<const float4*>(&W[(size_t)(k + 2) * ldw + col]);
        float4 w3 = *reinterpret_cast<const float4*>(&W[(size_t)(k + 3) * ldw + col]);
#pragma unroll
        for (int r = 0; r < 4; r++) {
            float4 a = *reinterpret_cast<const float4*>(&As[rg * 4 + r][k]);
            acc[r][0] += a.x * w0.x; acc[r][1] += a.x * w0.y; acc[r][2] += a.x * w0.z; acc[r][3] += a.x * w0.w;
            acc[r][0] += a.y * w1.x; acc[r][1] += a.y * w1.y; acc[r][2] += a.y * w1.z; acc[r][3] += a.y * w1.w;
            acc[r][0] += a.z * w2.x; acc[r][1] += a.z * w2.y; acc[r][2] += a.z * w2.z; acc[r][3] += a.z * w2.w;
            acc[r][0] += a.w * w3.x; acc[r][1] += a.w * w3.y; acc[r][2] += a.w * w3.z; acc[r][3] += a.w * w3.w;
        }
    }

    float4 bv = *reinterpret_cast<const float4*>(&bias[col]);
#pragma unroll
    for (int r = 0; r < 4; r++) {
        int gr = row0 + rg * 4 + r;
        if (gr >= rows) continue;
        float4 v = make_float4(acc[r][0] + bv.x, acc[r][1] + bv.y,
                               acc[r][2] + bv.z, acc[r][3] + bv.w);
        if (MODE == 2) {
            if (!fbmask[gr]) v = *reinterpret_cast<const float4*>(&fbx[(size_t)gr * HID + col]);
        }
        if (MODE >= 1) {
            v.x = fmaxf(v.x, 0.f); v.y = fmaxf(v.y, 0.f);
            v.z = fmaxf(v.z, 0.f); v.w = fmaxf(v.w, 0.f);
        }
        *reinterpret_cast<float4*>(&out[(size_t)gr * ldo + col]) = v;
    }
}

// ---------------- local-context single-query attention: one warp per (node, head) ----------------
__global__ void attn_kernel(const float* __restrict__ qkv,
                            const int* __restrict__ nbr_idx,
                            const int* __restrict__ nbr_mask,
                            float* __restrict__ o)
{
    int gw = (blockIdx.x * blockDim.x + threadIdx.x) >> 5;
    if (gw >= N_NODES * NHEAD) return;
    int lane = threadIdx.x & 31;
    int n = gw >> 2, h = gw & 3;

    float q = qkv[(size_t)n * 384 + h * 32 + lane];

    int idx[CTX];
    unsigned mbits = 1u;
    idx[0] = n;
#pragma unroll
    for (int c = 1; c < CTX; c++) {
        idx[c] = nbr_idx[n * K_NBR + c - 1];
        if (nbr_mask[n * K_NBR + c - 1]) mbits |= (1u << c);
    }

    float sc[CTX];
#pragma unroll
    for (int c = 0; c < CTX; c++)
        sc[c] = q * qkv[(size_t)idx[c] * 384 + 128 + h * 32 + lane];

    float mx = -1e30f;
#pragma unroll
    for (int c = 0; c < CTX; c++) {
        float s = sc[c];
        s += __shfl_xor_sync(0xffffffffu, s, 16);
        s += __shfl_xor_sync(0xffffffffu, s, 8);
        s += __shfl_xor_sync(0xffffffffu, s, 4);
        s += __shfl_xor_sync(0xffffffffu, s, 2);
        s += __shfl_xor_sync(0xffffffffu, s, 1);
        s *= 0.17677669529663687f;  // 1/sqrt(32)
        if (!((mbits >> c) & 1)) s = -1e9f;
        sc[c] = s;
        mx = fmaxf(mx, s);
    }
    float den = 0.f;
#pragma unroll
    for (int c = 0; c < CTX; c++) { sc[c] = __expf(sc[c] - mx); den += sc[c]; }

    float acc = 0.f;
#pragma unroll
    for (int c = 0; c < CTX; c++)
        acc += sc[c] * qkv[(size_t)idx[c] * 384 + 256 + h * 32 + lane];

    o[(size_t)n * HID + h * 32 + lane] = acc / den;
}

// ---------------- edge MLP layer 1: A row = [x[src](128), x[dst](128), ef(2)] @ eW1, relu ------
__global__ void edge_l1_kernel(const float* __restrict__ x,
                               const int* __restrict__ edges,
                               const float* __restrict__ ef,
                               const float* __restrict__ W,
                               const float* __restrict__ bias,
                               float* __restrict__ out)
{
    __shared__ __align__(16) float As[32][260];
    __shared__ int snd[64];
    int t = threadIdx.x;
    int e0 = blockIdx.x * 32;
    if (t < 64) snd[t] = edges[(size_t)(e0 + (t >> 1)) * 2 + (t & 1)];
    __syncthreads();
    for (int idx = t; idx < 32 * 256; idx += 256) {
        int r = idx >> 8, k = idx & 255;
        As[r][k] = x[(size_t)snd[2 * r + (k >> 7)] * HID + (k & 127)];
    }
    if (t < 64) {
        int r = t >> 1;
        As[r][256 + (t & 1)] = ef[(size_t)(e0 + r) * 2 + (t & 1)];
        if ((t & 1) == 0) { As[r][258] = 0.f; As[r][259] = 0.f; }
    }
    __syncthreads();

    int cg = t & 31, rg = t >> 5;
    int col = cg * 4;
    float acc[4][4] = {};
#pragma unroll 1
    for (int k = 0; k < 256; k += 4) {
        float4 w0 = *reinterpret_cast<const float4*>(&W[(size_t)(k + 0) * 128 + col]);
        float4 w1 = *reinterpret_cast<const float4*>(&W[(size_t)(k + 1) * 128 + col]);
        float4 w2 = *reinterpret_cast<const float4*>(&W[(size_t)(k + 2) * 128 + col]);
        float4 w3 = *reinterpret_cast<const float4*>(&W[(size_t)(k + 3) * 128 + col]);
#pragma unroll
        for (int r = 0; r < 4; r++) {
            float4 a = *reinterpret_cast<const float4*>(&As[rg * 4 + r][k]);
            acc[r][0] += a.x * w0.x; acc[r][1] += a.x * w0.y; acc[r][2] += a.x * w0.z; acc[r][3] += a.x * w0.w;
            acc[r][0] += a.y * w1.x; acc[r][1] += a.y * w1.y; acc[r][2] += a.y * w1.z; acc[r][3] += a.y * w1.w;
            acc[r][0] += a.z * w2.x; acc[r][1] += a.z * w2.y; acc[r][2] += a.z * w2.z; acc[r][3] += a.z * w2.w;
            acc[r][0] += a.w * w3.x; acc[r][1] += a.w * w3.y; acc[r][2] += a.w * w3.z; acc[r][3] += a.w * w3.w;
        }
    }
    for (int k = 256; k < 258; k++) {
        float4 w = *reinterpret_cast<const float4*>(&W[(size_t)k * 128 + col]);
#pragma unroll
        for (int r = 0; r < 4; r++) {
            float a = As[rg * 4 + r][k];
            acc[r][0] += a * w.x; acc[r][1] += a * w.y; acc[r][2] += a * w.z; acc[r][3] += a * w.w;
        }
    }
    float4 bv = *reinterpret_cast<const float4*>(&bias[col]);
#pragma unroll
    for (int r = 0; r < 4; r++) {
        int e = e0 + rg * 4 + r;
        float4 v = make_float4(fmaxf(acc[r][0] + bv.x, 0.f), fmaxf(acc[r][1] + bv.y, 0.f),
                               fmaxf(acc[r][2] + bv.z, 0.f), fmaxf(acc[r][3] + bv.w, 0.f));
        *reinterpret_cast<float4*>(&out[(size_t)e * HID + col]) = v;
    }
}

// ---------------- final edge logit: warp per edge, dot(h2[64], W3) + b3 ----------------
__global__ void edge_out_kernel(const float* __restrict__ h2,
                                const float* __restrict__ W3,
                                const float* __restrict__ b3,
                                float* __restrict__ out)
{
    int e = (blockIdx.x * blockDim.x + threadIdx.x) >> 5;
    if (e >= N_EDGES) return;
    int lane = threadIdx.x & 31;
    const float* h = h2 + (size_t)e * 64;
    float s = h[lane] * W3[lane] + h[lane + 32] * W3[lane + 32];
    s += __shfl_xor_sync(0xffffffffu, s, 16);
    s += __shfl_xor_sync(0xffffffffu, s, 8);
    s += __shfl_xor_sync(0xffffffffu, s, 4);
    s += __shfl_xor_sync(0xffffffffu, s, 2);
    s += __shfl_xor_sync(0xffffffffu, s, 1);
    if (lane == 0) out[e] = s + b3[0];
}

// ---------------- launch ----------------
extern "C" void kernel_launch(void* const* d_in, const int* in_sizes, int n_in,
                              void* d_out, int out_size)
{
    (void)in_sizes; (void)n_in; (void)out_size;
    const int*   type_idx   = (const int*)d_in[0];
    const int*   cat_idx    = (const int*)d_in[1];
    const int*   nbr_idx    = (const int*)d_in[2];
    const int*   nbr_mask   = (const int*)d_in[3];   // numpy bool assumed stored as int32
    const int*   edges      = (const int*)d_in[4];
    const float* log_deg    = (const float*)d_in[5];
    const float* edge_feats = (const float*)d_in[6];
    const float* type_embed = (const float*)d_in[7];
    const float* cat_embed0 = (const float*)d_in[8];
    const float* cat_embed1 = (const float*)d_in[9];
    const float* deg_W      = (const float*)d_in[10];
    const float* deg_b      = (const float*)d_in[11];
    const float* proj_W     = (const float*)d_in[12];
    const float* proj_b     = (const float*)d_in[13];
    const float* Wqkv       = (const float*)d_in[14];
    const float* bqkv       = (const float*)d_in[15];
    const float* Wo         = (const float*)d_in[16];
    const float* bo         = (const float*)d_in[17];
    const float* eW1        = (const float*)d_in[18];
    const float* eb1        = (const float*)d_in[19];
    const float* eW2        = (const float*)d_in[20];
    const float* eb2        = (const float*)d_in[21];
    const float* eW3        = (const float*)d_in[22];
    const float* eb3        = (const float*)d_in[23];
    float* out = (float*)d_out;

    float *feats, *xa, *xb, *qkvp, *op, *h1, *h2; int* has;
    cudaGetSymbolAddress((void**)&feats, g_feats);
    cudaGetSymbolAddress((void**)&xa, g_xa);
    cudaGetSymbolAddress((void**)&xb, g_xb);
    cudaGetSymbolAddress((void**)&qkvp, g_qkv);
    cudaGetSymbolAddress((void**)&op, g_o);
    cudaGetSymbolAddress((void**)&h1, g_h1);
    cudaGetSymbolAddress((void**)&h2, g_h2);
    cudaGetSymbolAddress((void**)&has, g_has);

    encode_kernel<<<(N_NODES * FEAT + 255) / 256, 256>>>(
        type_idx, cat_idx, log_deg, type_embed, cat_embed0, cat_embed1, deg_W, deg_b, feats);
    hasnbr_kernel<<<(N_NODES + 255) / 256, 256>>>(nbr_mask, has);

    dim3 gN((N_NODES + 31) / 32, 1);
    gemm_kernel<160, 128, 0><<<gN, 256>>>(feats, proj_W, 128, proj_b, xa, 128,
                                          N_NODES, nullptr, nullptr);

    float* xcur = xa;
    float* xnxt = xb;
    for (int l = 0; l < 3; l++) {
        gemm_kernel<128, 128, 0><<<dim3((N_NODES + 31) / 32, 3), 256>>>(
            xcur, Wqkv + (size_t)l * 128 * 384, 384, bqkv + (size_t)l * 384,
            qkvp, 384, N_NODES, nullptr, nullptr);
        attn_kernel<<<(N_NODES * NHEAD) / 8, 256>>>(qkvp, nbr_idx, nbr_mask, op);
        gemm_kernel<128, 128, 2><<<gN, 256>>>(
            op, Wo + (size_t)l * 128 * 128, 128, bo + (size_t)l * 128,
            xnxt, 128, N_NODES, xcur, has);
        float* tmp = xcur; xcur = xnxt; xnxt = tmp;
    }

    edge_l1_kernel<<<N_EDGES / 32, 256>>>(xcur, edges, edge_feats, eW1, eb1, h1);
    gemm_kernel<128, 64, 1><<<dim3(N_EDGES / 64, 1), 256>>>(
        h1, eW2, 64, eb2, h2, 64, N_EDGES, nullptr, nullptr);
    edge_out_kernel<<<N_EDGES / 8, 256>>>(h2, eW3, eb3, out);
}

// round 2
// speedup vs baseline: 1.1390x; 1.1390x over previous
#include <cuda_runtime.h>

#define N_NODES 50000
#define K_NBR   16
#define N_EDGES 200000
#define HID     128
#define NHEAD   4
#define FEAT    160
#define CTX     17

// ---------------- scratch ----------------
__device__ float g_feats[N_NODES * FEAT];
__device__ float g_xa[N_NODES * HID];
__device__ float g_xb[N_NODES * HID];
__device__ float g_qkv[N_NODES * 3 * HID];
__device__ float g_o[N_NODES * HID];
__device__ int   g_has[N_NODES];
__device__ float g_u[N_NODES * HID];
__device__ float g_w[N_NODES * HID];

// ---------------- node feature encoding ----------------
__global__ void encode_kernel(const int* __restrict__ type_idx,
                              const int* __restrict__ cat_idx,
                              const float* __restrict__ log_deg,
                              const float* __restrict__ type_embed,
                              const float* __restrict__ cat_embed0,
                              const float* __restrict__ cat_embed1,
                              const float* __restrict__ deg_W,
                              const float* __restrict__ deg_b,
                              float* __restrict__ feats)
{
    int i = blockIdx.x * blockDim.x + threadIdx.x;
    if (i >= N_NODES * FEAT) return;
    int n = i / FEAT, j = i - n * FEAT;
    float v;
    if (j < 64)        v = type_embed[type_idx[n] * 64 + j];
    else if (j < 96)   v = cat_embed0[cat_idx[2 * n] * 32 + (j - 64)];
    else if (j < 128)  v = cat_embed1[cat_idx[2 * n + 1] * 32 + (j - 96)];
    else {
        int jj = j - 128;
        v = fmaxf(log_deg[n] * deg_W[jj] + deg_b[jj], 0.f);
    }
    feats[i] = v;
}

__global__ void hasnbr_kernel(const int* __restrict__ nbr_mask, int* __restrict__ has)
{
    int n = blockIdx.x * blockDim.x + threadIdx.x;
    if (n >= N_NODES) return;
    int a = 0;
#pragma unroll
    for (int j = 0; j < K_NBR; j++) a |= nbr_mask[n * K_NBR + j];
    has[n] = a ? 1 : 0;
}

// ---------------- tiled GEMM, 64x128 tile, A and W staged in shared ----------------
// out[r, colbase+c] = sum_k A[r,k] * W[k, colbase+c] (+ bias)
// MODE 0: plain; MODE 2: relu(where(fbmask, val, fbx))
template <int KDIM, int MODE, bool HASBIAS>
__global__ void gemm128_kernel(const float* __restrict__ A,
                               const float* __restrict__ W, int ldw,
                               const float* __restrict__ bias,
                               float* __restrict__ out, int ldo,
                               int rows,
                               const float* __restrict__ fbx,
                               const int* __restrict__ fbmask)
{
    static_assert(KDIM % 16 == 0, "KDIM % 16");
    __shared__ __align__(16) float As[16][68];    // k-major, padded
    __shared__ __align__(16) float Ws[16][128];

    int t = threadIdx.x;
    int row0 = blockIdx.x * 64;
    int colbase = blockIdx.y * 128;

    int lrow = t >> 2;              // 0..63 for A loads
    int lk4  = (t & 3) << 2;        // 0,4,8,12
    int tm = t >> 4;                // 0..15 -> rows 4*tm
    int tn = t & 15;                // 0..15 -> cols 8*tn

    float acc[4][8] = {};

    for (int kk = 0; kk < KDIM; kk += 16) {
        __syncthreads();
        // stage A (transpose to k-major)
        {
            int gr = row0 + lrow;
            float4 a = make_float4(0.f, 0.f, 0.f, 0.f);
            if (gr < rows)
                a = *reinterpret_cast<const float4*>(&A[(size_t)gr * KDIM + kk + lk4]);
            As[lk4 + 0][lrow] = a.x;
            As[lk4 + 1][lrow] = a.y;
            As[lk4 + 2][lrow] = a.z;
            As[lk4 + 3][lrow] = a.w;
        }
        // stage W: 16 x 128 = 512 float4
#pragma unroll
        for (int it = 0; it < 2; it++) {
            int fidx = t + it * 256;
            int r = fidx >> 5, c4 = (fidx & 31) << 2;
            *reinterpret_cast<float4*>(&Ws[r][c4]) =
                *reinterpret_cast<const float4*>(&W[(size_t)(kk + r) * ldw + colbase + c4]);
        }
        __syncthreads();

#pragma unroll
        for (int k = 0; k < 16; k++) {
            float4 a  = *reinterpret_cast<const float4*>(&As[k][4 * tm]);
            float4 w0 = *reinterpret_cast<const float4*>(&Ws[k][8 * tn]);
            float4 w1 = *reinterpret_cast<const float4*>(&Ws[k][8 * tn + 4]);
            float av[4] = {a.x, a.y, a.z, a.w};
#pragma unroll
            for (int r = 0; r < 4; r++) {
                acc[r][0] += av[r] * w0.x; acc[r][1] += av[r] * w0.y;
                acc[r][2] += av[r] * w0.z; acc[r][3] += av[r] * w0.w;
                acc[r][4] += av[r] * w1.x; acc[r][5] += av[r] * w1.y;
                acc[r][6] += av[r] * w1.z; acc[r][7] += av[r] * w1.w;
            }
        }
    }

    int col = colbase + 8 * tn;
    float4 b0 = make_float4(0.f, 0.f, 0.f, 0.f), b1 = b0;
    if (HASBIAS) {
        b0 = *reinterpret_cast<const float4*>(&bias[col]);
        b1 = *reinterpret_cast<const float4*>(&bias[col + 4]);
    }
#pragma unroll
    for (int r = 0; r < 4; r++) {
        int gr = row0 + 4 * tm + r;
        if (gr >= rows) continue;
        float4 v0 = make_float4(acc[r][0] + b0.x, acc[r][1] + b0.y,
                                acc[r][2] + b0.z, acc[r][3] + b0.w);
        float4 v1 = make_float4(acc[r][4] + b1.x, acc[r][5] + b1.y,
                                acc[r][6] + b1.z, acc[r][7] + b1.w);
        if (MODE == 2) {
            if (!fbmask[gr]) {
                v0 = *reinterpret_cast<const float4*>(&fbx[(size_t)gr * HID + col]);
                v1 = *reinterpret_cast<const float4*>(&fbx[(size_t)gr * HID + col + 4]);
            }
            v0.x = fmaxf(v0.x, 0.f); v0.y = fmaxf(v0.y, 0.f);
            v0.z = fmaxf(v0.z, 0.f); v0.w = fmaxf(v0.w, 0.f);
            v1.x = fmaxf(v1.x, 0.f); v1.y = fmaxf(v1.y, 0.f);
            v1.z = fmaxf(v1.z, 0.f); v1.w = fmaxf(v1.w, 0.f);
        }
        *reinterpret_cast<float4*>(&out[(size_t)gr * ldo + col]) = v0;
        *reinterpret_cast<float4*>(&out[(size_t)gr * ldo + col + 4]) = v1;
    }
}

// ---------------- local-context attention: one warp per (node, head) ----------------
__global__ void attn_kernel(const float* __restrict__ qkv,
                            const int* __restrict__ nbr_idx,
                            const int* __restrict__ nbr_mask,
                            float* __restrict__ o)
{
    int gw = (blockIdx.x * blockDim.x + threadIdx.x) >> 5;
    if (gw >= N_NODES * NHEAD) return;
    int lane = threadIdx.x & 31;
    int n = gw >> 2, h = gw & 3;

    float q = qkv[(size_t)n * 384 + h * 32 + lane];

    int idx[CTX];
    unsigned mbits = 1u;
    idx[0] = n;
#pragma unroll
    for (int c = 1; c < CTX; c++) {
        idx[c] = nbr_idx[n * K_NBR + c - 1];
        if (nbr_mask[n * K_NBR + c - 1]) mbits |= (1u << c);
    }

    float sc[CTX];
#pragma unroll
    for (int c = 0; c < CTX; c++)
        sc[c] = q * qkv[(size_t)idx[c] * 384 + 128 + h * 32 + lane];

    float mx = -1e30f;
#pragma unroll
    for (int c = 0; c < CTX; c++) {
        float s = sc[c];
        s += __shfl_xor_sync(0xffffffffu, s, 16);
        s += __shfl_xor_sync(0xffffffffu, s, 8);
        s += __shfl_xor_sync(0xffffffffu, s, 4);
        s += __shfl_xor_sync(0xffffffffu, s, 2);
        s += __shfl_xor_sync(0xffffffffu, s, 1);
        s *= 0.17677669529663687f;  // 1/sqrt(32)
        if (!((mbits >> c) & 1)) s = -1e9f;
        sc[c] = s;
        mx = fmaxf(mx, s);
    }
    float den = 0.f;
#pragma unroll
    for (int c = 0; c < CTX; c++) { sc[c] = __expf(sc[c] - mx); den += sc[c]; }

    float acc = 0.f;
#pragma unroll
    for (int c = 0; c < CTX; c++)
        acc += sc[c] * qkv[(size_t)idx[c] * 384 + 256 + h * 32 + lane];

    o[(size_t)n * HID + h * 32 + lane] = acc / den;
}

// ---------------- fused edge MLP: h1 = relu(u[s]+w[d]+ef@Wef), h2 = relu(h1@W2+b2), logit = h2@W3+b3
// 256 threads = 8 warps, 2 edges per warp -> 16 edges per block
__global__ void edge_fused_kernel(const float* __restrict__ u,
                                  const float* __restrict__ w,
                                  const int* __restrict__ edges,
                                  const float* __restrict__ ef,
                                  const float* __restrict__ eW1,   // [258][128]
                                  const float* __restrict__ eW2,   // [128][64]
                                  const float* __restrict__ eb2,
                                  const float* __restrict__ eW3,   // [64]
                                  const float* __restrict__ eb3,
                                  float* __restrict__ out)
{
    __shared__ __align__(16) float W2t[64][132];   // transposed, padded
    __shared__ __align__(16) float h1s[16][128];
    __shared__ float W3s[64];
    __shared__ float b2s[64];

    int t = threadIdx.x;
    int lane = t & 31, wid = t >> 5;
    int e0 = blockIdx.x * 16;

    // stage eW2 transposed: eW2[j][c] -> W2t[c][j]
#pragma unroll
    for (int it = 0; it < 8; it++) {
        int fidx = t + it * 256;              // 0..2047
        int j = fidx >> 4, c4 = (fidx & 15) << 2;
        float4 v = *reinterpret_cast<const float4*>(&eW2[(size_t)j * 64 + c4]);
        W2t[c4 + 0][j] = v.x;
        W2t[c4 + 1][j] = v.y;
        W2t[c4 + 2][j] = v.z;
        W2t[c4 + 3][j] = v.w;
    }
    if (t < 64) { W3s[t] = eW3[t]; b2s[t] = eb2[t]; }

    const float* wef0 = eW1 + 256 * 128;
    const float* wef1 = eW1 + 257 * 128;
    float4 we0 = *reinterpret_cast<const float4*>(&wef0[lane * 4]);
    float4 we1 = *reinterpret_cast<const float4*>(&wef1[lane * 4]);

    // phase 1: h1 for this warp's 2 edges
#pragma unroll
    for (int ee = 0; ee < 2; ee++) {
        int el = wid * 2 + ee;
        int e = e0 + el;
        int s = edges[2 * e], d = edges[2 * e + 1];
        float f0 = ef[2 * e], f1 = ef[2 * e + 1];
        float4 uu = *reinterpret_cast<const float4*>(&u[(size_t)s * HID + lane * 4]);
        float4 ww = *reinterpret_cast<const float4*>(&w[(size_t)d * HID + lane * 4]);
        float4 h;
        h.x = fmaxf(uu.x + ww.x + f0 * we0.x + f1 * we1.x, 0.f);
        h.y = fmaxf(uu.y + ww.y + f0 * we0.y + f1 * we1.y, 0.f);
        h.z = fmaxf(uu.z + ww.z + f0 * we0.z + f1 * we1.z, 0.f);
        h.w = fmaxf(uu.w + ww.w + f0 * we0.w + f1 * we1.w, 0.f);
        *reinterpret_cast<float4*>(&h1s[el][lane * 4]) = h;
    }
    __syncthreads();

    // phase 2: h2 (cols lane, lane+32) for 2 edges, then logit
    float acc00 = 0.f, acc01 = 0.f, acc10 = 0.f, acc11 = 0.f;
    int el0 = wid * 2, el1 = wid * 2 + 1;
#pragma unroll
    for (int j4 = 0; j4 < 128; j4 += 4) {
        float4 w0 = *reinterpret_cast<const float4*>(&W2t[lane][j4]);
        float4 w1 = *reinterpret_cast<const float4*>(&W2t[lane + 32][j4]);
        float4 h0 = *reinterpret_cast<const float4*>(&h1s[el0][j4]);
        float4 h1 = *reinterpret_cast<const float4*>(&h1s[el1][j4]);
        acc00 += h0.x * w0.x + h0.y * w0.y + h0.z * w0.z + h0.w * w0.w;
        acc01 += h0.x * w1.x + h0.y * w1.y + h0.z * w1.z + h0.w * w1.w;
        acc10 += h1.x * w0.x + h1.y * w0.y + h1.z * w0.z + h1.w * w0.w;
        acc11 += h1.x * w1.x + h1.y * w1.y + h1.z * w1.z + h1.w * w1.w;
    }
    float b0 = b2s[lane], b1 = b2s[lane + 32];
    float w3a = W3s[lane], w3b = W3s[lane + 32];

    float p0 = fmaxf(acc00 + b0, 0.f) * w3a + fmaxf(acc01 + b1, 0.f) * w3b;
    float p1 = fmaxf(acc10 + b0, 0.f) * w3a + fmaxf(acc11 + b1, 0.f) * w3b;

    p0 += __shfl_xor_sync(0xffffffffu, p0, 16);
    p0 += __shfl_xor_sync(0xffffffffu, p0, 8);
    p0 += __shfl_xor_sync(0xffffffffu, p0, 4);
    p0 += __shfl_xor_sync(0xffffffffu, p0, 2);
    p0 += __shfl_xor_sync(0xffffffffu, p0, 1);
    p1 += __shfl_xor_sync(0xffffffffu, p1, 16);
    p1 += __shfl_xor_sync(0xffffffffu, p1, 8);
    p1 += __shfl_xor_sync(0xffffffffu, p1, 4);
    p1 += __shfl_xor_sync(0xffffffffu, p1, 2);
    p1 += __shfl_xor_sync(0xffffffffu, p1, 1);
    if (lane == 0) {
        out[e0 + el0] = p0 + eb3[0];
        out[e0 + el1] = p1 + eb3[0];
    }
}

// ---------------- launch ----------------
extern "C" void kernel_launch(void* const* d_in, const int* in_sizes, int n_in,
                              void* d_out, int out_size)
{
    (void)in_sizes; (void)n_in; (void)out_size;
    const int*   type_idx   = (const int*)d_in[0];
    const int*   cat_idx    = (const int*)d_in[1];
    const int*   nbr_idx    = (const int*)d_in[2];
    const int*   nbr_mask   = (const int*)d_in[3];
    const int*   edges      = (const int*)d_in[4];
    const float* log_deg    = (const float*)d_in[5];
    const float* edge_feats = (const float*)d_in[6];
    const float* type_embed = (const float*)d_in[7];
    const float* cat_embed0 = (const float*)d_in[8];
    const float* cat_embed1 = (const float*)d_in[9];
    const float* deg_W      = (const float*)d_in[10];
    const float* deg_b      = (const float*)d_in[11];
    const float* proj_W     = (const float*)d_in[12];
    const float* proj_b     = (const float*)d_in[13];
    const float* Wqkv       = (const float*)d_in[14];
    const float* bqkv       = (const float*)d_in[15];
    const float* Wo         = (const float*)d_in[16];
    const float* bo         = (const float*)d_in[17];
    const float* eW1        = (const float*)d_in[18];
    const float* eb1        = (const float*)d_in[19];
    const float* eW2        = (const float*)d_in[20];
    const float* eb2        = (const float*)d_in[21];
    const float* eW3        = (const float*)d_in[22];
    const float* eb3        = (const float*)d_in[23];
    float* out = (float*)d_out;

    float *feats, *xa, *xb, *qkvp, *op, *up, *wp; int* has;
    cudaGetSymbolAddress((void**)&feats, g_feats);
    cudaGetSymbolAddress((void**)&xa, g_xa);
    cudaGetSymbolAddress((void**)&xb, g_xb);
    cudaGetSymbolAddress((void**)&qkvp, g_qkv);
    cudaGetSymbolAddress((void**)&op, g_o);
    cudaGetSymbolAddress((void**)&up, g_u);
    cudaGetSymbolAddress((void**)&wp, g_w);
    cudaGetSymbolAddress((void**)&has, g_has);

    encode_kernel<<<(N_NODES * FEAT + 255) / 256, 256>>>(
        type_idx, cat_idx, log_deg, type_embed, cat_embed0, cat_embed1, deg_W, deg_b, feats);
    hasnbr_kernel<<<(N_NODES + 255) / 256, 256>>>(nbr_mask, has);

    int gN = (N_NODES + 63) / 64;
    gemm128_kernel<160, 0, true><<<gN, 256>>>(feats, proj_W, 128, proj_b,
                                              xa, 128, N_NODES, nullptr, nullptr);

    float* xcur = xa;
    float* xnxt = xb;
    for (int l = 0; l < 3; l++) {
        gemm128_kernel<128, 0, true><<<dim3(gN, 3), 256>>>(
            xcur, Wqkv + (size_t)l * 128 * 384, 384, bqkv + (size_t)l * 384,
            qkvp, 384, N_NODES, nullptr, nullptr);
        attn_kernel<<<(N_NODES * NHEAD) / 8, 256>>>(qkvp, nbr_idx, nbr_mask, op);
        gemm128_kernel<128, 2, true><<<gN, 256>>>(
            op, Wo + (size_t)l * 128 * 128, 128, bo + (size_t)l * 128,
            xnxt, 128, N_NODES, xcur, has);
        float* tmp = xcur; xcur = xnxt; xnxt = tmp;
    }

    // edge MLP: u = x @ W_top + eb1 ; w = x @ W_bot
    gemm128_kernel<128, 0, true><<<gN, 256>>>(xcur, eW1, 128, eb1,
                                              up, 128, N_NODES, nullptr, nullptr);
    gemm128_kernel<128, 0, false><<<gN, 256>>>(xcur, eW1 + 128 * 128, 128, nullptr,
                                               wp, 128, N_NODES, nullptr, nullptr);
    edge_fused_kernel<<<N_EDGES / 16, 256>>>(up, wp, edges, edge_feats,
                                             eW1, eW2, eb2, eW3, eb3, out);
}

// round 3
// speedup vs baseline: 2.5634x; 2.2506x over previous
#include <cuda_runtime.h>
#include <cstdint>

#define N_NODES 50000
#define K_NBR   16
#define N_EDGES 200000
#define HID     128
#define NHEAD   4
#define FEAT    160
#define CTX     17

// ---------------- scratch ----------------
__device__ float g_feats[N_NODES * FEAT];
__device__ float g_xa[N_NODES * HID];
__device__ float g_xb[N_NODES * HID];
__device__ float g_qkv[N_NODES * 3 * HID];
__device__ float g_o[N_NODES * HID];
__device__ int   g_has[N_NODES];
__device__ float g_u[N_NODES * HID];
__device__ float g_w[N_NODES * HID];

__device__ __forceinline__ float to_tf32(float x) {
    uint32_t u;
    asm("cvt.rna.tf32.f32 %0, %1;" : "=r"(u) : "f"(x));
    return __uint_as_float(u);
}

__device__ __forceinline__ void mma_tf32(float c[4], const uint32_t a[4],
                                         uint32_t b0, uint32_t b1) {
    asm volatile(
        "mma.sync.aligned.m16n8k8.row.col.f32.tf32.tf32.f32 "
        "{%0,%1,%2,%3}, {%4,%5,%6,%7}, {%8,%9}, {%0,%1,%2,%3};\n"
        : "+f"(c[0]), "+f"(c[1]), "+f"(c[2]), "+f"(c[3])
        : "r"(a[0]), "r"(a[1]), "r"(a[2]), "r"(a[3]), "r"(b0), "r"(b1));
}

// ---------------- node feature encoding ----------------
__global__ void encode_kernel(const int* __restrict__ type_idx,
                              const int* __restrict__ cat_idx,
                              const float* __restrict__ log_deg,
                              const float* __restrict__ type_embed,
                              const float* __restrict__ cat_embed0,
                              const float* __restrict__ cat_embed1,
                              const float* __restrict__ deg_W,
                              const float* __restrict__ deg_b,
                              float* __restrict__ feats)
{
    int i = blockIdx.x * blockDim.x + threadIdx.x;
    if (i >= N_NODES * FEAT) return;
    int n = i / FEAT, j = i - n * FEAT;
    float v;
    if (j < 64)        v = type_embed[type_idx[n] * 64 + j];
    else if (j < 96)   v = cat_embed0[cat_idx[2 * n] * 32 + (j - 64)];
    else if (j < 128)  v = cat_embed1[cat_idx[2 * n + 1] * 32 + (j - 96)];
    else {
        int jj = j - 128;
        v = fmaxf(log_deg[n] * deg_W[jj] + deg_b[jj], 0.f);
    }
    feats[i] = v;
}

__global__ void hasnbr_kernel(const int* __restrict__ nbr_mask, int* __restrict__ has)
{
    int n = blockIdx.x * blockDim.x + threadIdx.x;
    if (n >= N_NODES) return;
    int a = 0;
#pragma unroll
    for (int j = 0; j < K_NBR; j++) a |= nbr_mask[n * K_NBR + j];
    has[n] = a ? 1 : 0;
}

// ---------------- tensor-core GEMM (tf32 mma.sync), 128x128 block tile ----------------
// out[r, colbase+c] = sum_k A[r,k] * W[k, colbase+c] (+bias)
// MODE 0: plain; MODE 2: relu(where(fbmask, val, fbx))
template <int KDIM, int MODE, bool HASBIAS>
__global__ void __launch_bounds__(256, 2)
gemm_tc(const float* __restrict__ A, const float* __restrict__ W, int ldw,
        const float* __restrict__ bias, float* __restrict__ out, int ldo,
        int rows, const float* __restrict__ fbx, const int* __restrict__ fbmask)
{
    static_assert(KDIM % 32 == 0, "KDIM % 32");
    __shared__ __align__(16) float As[128][36];   // pad 36 -> frag LDS conflict-free
    __shared__ __align__(16) float Bs[32][136];   // pad 136 -> frag LDS conflict-free

    int t = threadIdx.x, lane = t & 31, wid = t >> 5;
    int g = lane >> 2, tig = lane & 3;
    int wm = wid & 3, wn = wid >> 2;              // 4(m) x 2(n) warps, warp tile 32x64
    int row0 = blockIdx.x * 128;
    int colbase = blockIdx.y * 128;

    float acc[2][8][4];
#pragma unroll
    for (int i = 0; i < 2; i++)
#pragma unroll
        for (int j = 0; j < 8; j++)
#pragma unroll
            for (int k = 0; k < 4; k++) acc[i][j][k] = 0.f;

#pragma unroll 1
    for (int kt = 0; kt < KDIM / 32; kt++) {
        int kk = kt * 32;
        __syncthreads();
        // stage A: 128 x 32, 4 float4 per thread
#pragma unroll
        for (int i = 0; i < 4; i++) {
            int id = t + i * 256;
            int r = id >> 3;
            int c0 = (id & 7) << 2;
            float4 a = make_float4(0.f, 0.f, 0.f, 0.f);
            int gr = row0 + r;
            if (gr < rows) a = *reinterpret_cast<const float4*>(&A[(size_t)gr * KDIM + kk + c0]);
            float4 av = make_float4(to_tf32(a.x), to_tf32(a.y), to_tf32(a.z), to_tf32(a.w));
            *reinterpret_cast<float4*>(&As[r][c0]) = av;
        }
        // stage B: 32 x 128, 4 float4 per thread
#pragma unroll
        for (int i = 0; i < 4; i++) {
            int id = t + i * 256;
            int kr = id >> 5;
            int c0 = (id & 31) << 2;
            float4 w = *reinterpret_cast<const float4*>(&W[(size_t)(kk + kr) * ldw + colbase + c0]);
            float4 wv = make_float4(to_tf32(w.x), to_tf32(w.y), to_tf32(w.z), to_tf32(w.w));
            *reinterpret_cast<float4*>(&Bs[kr][c0]) = wv;
        }
        __syncthreads();

#pragma unroll
        for (int ks = 0; ks < 4; ks++) {
            int kb = ks * 8;
            uint32_t a[2][4];
#pragma unroll
            for (int mt = 0; mt < 2; mt++) {
                int rb = wm * 32 + mt * 16;
                a[mt][0] = __float_as_uint(As[rb + g][kb + tig]);
                a[mt][1] = __float_as_uint(As[rb + g + 8][kb + tig]);
                a[mt][2] = __float_as_uint(As[rb + g][kb + tig + 4]);
                a[mt][3] = __float_as_uint(As[rb + g + 8][kb + tig + 4]);
            }
#pragma unroll
            for (int nt = 0; nt < 8; nt++) {
                int cb = wn * 64 + nt * 8;
                uint32_t b0 = __float_as_uint(Bs[kb + tig][cb + g]);
                uint32_t b1 = __float_as_uint(Bs[kb + tig + 4][cb + g]);
                mma_tf32(acc[0][nt], a[0], b0, b1);
                mma_tf32(acc[1][nt], a[1], b0, b1);
            }
        }
    }

    // epilogue
#pragma unroll
    for (int mt = 0; mt < 2; mt++) {
#pragma unroll
        for (int half = 0; half < 2; half++) {
            int gr = row0 + wm * 32 + mt * 16 + g + half * 8;
            if (gr >= rows) continue;
            bool fb = false;
            if (MODE == 2) fb = (fbmask[gr] == 0);
#pragma unroll
            for (int nt = 0; nt < 8; nt++) {
                int col = colbase + wn * 64 + nt * 8 + tig * 2;
                float v0 = acc[mt][nt][half * 2 + 0];
                float v1 = acc[mt][nt][half * 2 + 1];
                if (HASBIAS) { v0 += bias[col]; v1 += bias[col + 1]; }
                if (MODE == 2) {
                    if (fb) {
                        float2 f = *reinterpret_cast<const float2*>(&fbx[(size_t)gr * HID + col]);
                        v0 = f.x; v1 = f.y;
                    }
                    v0 = fmaxf(v0, 0.f);
                    v1 = fmaxf(v1, 0.f);
                }
                *reinterpret_cast<float2*>(&out[(size_t)gr * ldo + col]) = make_float2(v0, v1);
            }
        }
    }
}

// ---------------- local-context attention: one warp per NODE (all 4 heads) ----------------
__global__ void attn_kernel(const float* __restrict__ qkv,
                            const int* __restrict__ nbr_idx,
                            const int* __restrict__ nbr_mask,
                            float* __restrict__ o)
{
    int n = (blockIdx.x * blockDim.x + threadIdx.x) >> 5;
    if (n >= N_NODES) return;
    int lane = threadIdx.x & 31;
    int off = lane * 4;                   // head h = lane>>3, dims (lane&7)*4..+3

    float4 q = *reinterpret_cast<const float4*>(&qkv[(size_t)n * 384 + off]);

    int nb = 0, mk = 0;
    if (lane < 16) {
        nb = nbr_idx[n * K_NBR + lane];
        mk = nbr_mask[n * K_NBR + lane];
    }
    unsigned mb = __ballot_sync(0xffffffffu, (lane < 16) && mk);  // bits 0..15

    int idxs[CTX];
    float sc[CTX];
    idxs[0] = n;
#pragma unroll
    for (int c = 0; c < CTX; c++) {
        int id = (c == 0) ? n : __shfl_sync(0xffffffffu, nb, c - 1);
        idxs[c] = id;
        float4 k4 = *reinterpret_cast<const float4*>(&qkv[(size_t)id * 384 + 128 + off]);
        float s = q.x * k4.x + q.y * k4.y + q.z * k4.z + q.w * k4.w;
        s += __shfl_xor_sync(0xffffffffu, s, 4);
        s += __shfl_xor_sync(0xffffffffu, s, 2);
        s += __shfl_xor_sync(0xffffffffu, s, 1);
        s *= 0.17677669529663687f;        // 1/sqrt(32)
        if (c > 0 && !((mb >> (c - 1)) & 1)) s = -1e9f;
        sc[c] = s;
    }

    float mx = sc[0];
#pragma unroll
    for (int c = 1; c < CTX; c++) mx = fmaxf(mx, sc[c]);
    float den = 0.f;
#pragma unroll
    for (int c = 0; c < CTX; c++) { sc[c] = __expf(sc[c] - mx); den += sc[c]; }
    float inv = 1.f / den;

    float4 av = make_float4(0.f, 0.f, 0.f, 0.f);
#pragma unroll
    for (int c = 0; c < CTX; c++) {
        float4 v4 = *reinterpret_cast<const float4*>(&qkv[(size_t)idxs[c] * 384 + 256 + off]);
        float p = sc[c];
        av.x += p * v4.x; av.y += p * v4.y; av.z += p * v4.z; av.w += p * v4.w;
    }
    av.x *= inv; av.y *= inv; av.z *= inv; av.w *= inv;
    *reinterpret_cast<float4*>(&o[(size_t)n * HID + off]) = av;
}

// ---------------- fused edge MLP ----------------
__global__ void edge_fused_kernel(const float* __restrict__ u,
                                  const float* __restrict__ w,
                                  const int* __restrict__ edges,
                                  const float* __restrict__ ef,
                                  const float* __restrict__ eW1,
                                  const float* __restrict__ eW2,
                                  const float* __restrict__ eb2,
                                  const float* __restrict__ eW3,
                                  const float* __restrict__ eb3,
                                  float* __restrict__ out)
{
    __shared__ __align__(16) float W2t[64][132];
    __shared__ __align__(16) float h1s[16][128];
    __shared__ float W3s[64];
    __shared__ float b2s[64];

    int t = threadIdx.x;
    int lane = t & 31, wid = t >> 5;
    int e0 = blockIdx.x * 16;

#pragma unroll
    for (int it = 0; it < 8; it++) {
        int fidx = t + it * 256;
        int j = fidx >> 4, c4 = (fidx & 15) << 2;
        float4 v = *reinterpret_cast<const float4*>(&eW2[(size_t)j * 64 + c4]);
        W2t[c4 + 0][j] = v.x;
        W2t[c4 + 1][j] = v.y;
        W2t[c4 + 2][j] = v.z;
        W2t[c4 + 3][j] = v.w;
    }
    if (t < 64) { W3s[t] = eW3[t]; b2s[t] = eb2[t]; }

    const float* wef0 = eW1 + 256 * 128;
    const float* wef1 = eW1 + 257 * 128;
    float4 we0 = *reinterpret_cast<const float4*>(&wef0[lane * 4]);
    float4 we1 = *reinterpret_cast<const float4*>(&wef1[lane * 4]);

#pragma unroll
    for (int ee = 0; ee < 2; ee++) {
        int el = wid * 2 + ee;
        int e = e0 + el;
        int s = edges[2 * e], d = edges[2 * e + 1];
        float f0 = ef[2 * e], f1 = ef[2 * e + 1];
        float4 uu = *reinterpret_cast<const float4*>(&u[(size_t)s * HID + lane * 4]);
        float4 ww = *reinterpret_cast<const float4*>(&w[(size_t)d * HID + lane * 4]);
        float4 h;
        h.x = fmaxf(uu.x + ww.x + f0 * we0.x + f1 * we1.x, 0.f);
        h.y = fmaxf(uu.y + ww.y + f0 * we0.y + f1 * we1.y, 0.f);
        h.z = fmaxf(uu.z + ww.z + f0 * we0.z + f1 * we1.z, 0.f);
        h.w = fmaxf(uu.w + ww.w + f0 * we0.w + f1 * we1.w, 0.f);
        *reinterpret_cast<float4*>(&h1s[el][lane * 4]) = h;
    }
    __syncthreads();

    float acc00 = 0.f, acc01 = 0.f, acc10 = 0.f, acc11 = 0.f;
    int el0 = wid * 2, el1 = wid * 2 + 1;
#pragma unroll
    for (int j4 = 0; j4 < 128; j4 += 4) {
        float4 w0 = *reinterpret_cast<const float4*>(&W2t[lane][j4]);
        float4 w1 = *reinterpret_cast<const float4*>(&W2t[lane + 32][j4]);
        float4 h0 = *reinterpret_cast<const float4*>(&h1s[el0][j4]);
        float4 h1 = *reinterpret_cast<const float4*>(&h1s[el1][j4]);
        acc00 += h0.x * w0.x + h0.y * w0.y + h0.z * w0.z + h0.w * w0.w;
        acc01 += h0.x * w1.x + h0.y * w1.y + h0.z * w1.z + h0.w * w1.w;
        acc10 += h1.x * w0.x + h1.y * w0.y + h1.z * w0.z + h1.w * w0.w;
        acc11 += h1.x * w1.x + h1.y * w1.y + h1.z * w1.z + h1.w * w1.w;
    }
    float b0 = b2s[lane], b1 = b2s[lane + 32];
    float w3a = W3s[lane], w3b = W3s[lane + 32];

    float p0 = fmaxf(acc00 + b0, 0.f) * w3a + fmaxf(acc01 + b1, 0.f) * w3b;
    float p1 = fmaxf(acc10 + b0, 0.f) * w3a + fmaxf(acc11 + b1, 0.f) * w3b;

    p0 += __shfl_xor_sync(0xffffffffu, p0, 16);
    p0 += __shfl_xor_sync(0xffffffffu, p0, 8);
    p0 += __shfl_xor_sync(0xffffffffu, p0, 4);
    p0 += __shfl_xor_sync(0xffffffffu, p0, 2);
    p0 += __shfl_xor_sync(0xffffffffu, p0, 1);
    p1 += __shfl_xor_sync(0xffffffffu, p1, 16);
    p1 += __shfl_xor_sync(0xffffffffu, p1, 8);
    p1 += __shfl_xor_sync(0xffffffffu, p1, 4);
    p1 += __shfl_xor_sync(0xffffffffu, p1, 2);
    p1 += __shfl_xor_sync(0xffffffffu, p1, 1);
    if (lane == 0) {
        out[e0 + el0] = p0 + eb3[0];
        out[e0 + el1] = p1 + eb3[0];
    }
}

// ---------------- launch ----------------
extern "C" void kernel_launch(void* const* d_in, const int* in_sizes, int n_in,
                              void* d_out, int out_size)
{
    (void)in_sizes; (void)n_in; (void)out_size;
    const int*   type_idx   = (const int*)d_in[0];
    const int*   cat_idx    = (const int*)d_in[1];
    const int*   nbr_idx    = (const int*)d_in[2];
    const int*   nbr_mask   = (const int*)d_in[3];
    const int*   edges      = (const int*)d_in[4];
    const float* log_deg    = (const float*)d_in[5];
    const float* edge_feats = (const float*)d_in[6];
    const float* type_embed = (const float*)d_in[7];
    const float* cat_embed0 = (const float*)d_in[8];
    const float* cat_embed1 = (const float*)d_in[9];
    const float* deg_W      = (const float*)d_in[10];
    const float* deg_b      = (const float*)d_in[11];
    const float* proj_W     = (const float*)d_in[12];
    const float* proj_b     = (const float*)d_in[13];
    const float* Wqkv       = (const float*)d_in[14];
    const float* bqkv       = (const float*)d_in[15];
    const float* Wo         = (const float*)d_in[16];
    const float* bo         = (const float*)d_in[17];
    const float* eW1        = (const float*)d_in[18];
    const float* eb1        = (const float*)d_in[19];
    const float* eW2        = (const float*)d_in[20];
    const float* eb2        = (const float*)d_in[21];
    const float* eW3        = (const float*)d_in[22];
    const float* eb3        = (const float*)d_in[23];
    float* out = (float*)d_out;

    float *feats, *xa, *xb, *qkvp, *op, *up, *wp; int* has;
    cudaGetSymbolAddress((void**)&feats, g_feats);
    cudaGetSymbolAddress((void**)&xa, g_xa);
    cudaGetSymbolAddress((void**)&xb, g_xb);
    cudaGetSymbolAddress((void**)&qkvp, g_qkv);
    cudaGetSymbolAddress((void**)&op, g_o);
    cudaGetSymbolAddress((void**)&up, g_u);
    cudaGetSymbolAddress((void**)&wp, g_w);
    cudaGetSymbolAddress((void**)&has, g_has);

    encode_kernel<<<(N_NODES * FEAT + 255) / 256, 256>>>(
        type_idx, cat_idx, log_deg, type_embed, cat_embed0, cat_embed1, deg_W, deg_b, feats);
    hasnbr_kernel<<<(N_NODES + 255) / 256, 256>>>(nbr_mask, has);

    int gN = (N_NODES + 127) / 128;   // 391
    gemm_tc<160, 0, true><<<gN, 256>>>(feats, proj_W, 128, proj_b,
                                       xa, 128, N_NODES, nullptr, nullptr);

    float* xcur = xa;
    float* xnxt = xb;
    for (int l = 0; l < 3; l++) {
        gemm_tc<128, 0, true><<<dim3(gN, 3), 256>>>(
            xcur, Wqkv + (size_t)l * 128 * 384, 384, bqkv + (size_t)l * 384,
            qkvp, 384, N_NODES, nullptr, nullptr);
        attn_kernel<<<(N_NODES + 7) / 8, 256>>>(qkvp, nbr_idx, nbr_mask, op);
        gemm_tc<128, 2, true><<<gN, 256>>>(
            op, Wo + (size_t)l * 128 * 128, 128, bo + (size_t)l * 128,
            xnxt, 128, N_NODES, xcur, has);
        float* tmp = xcur; xcur = xnxt; xnxt = tmp;
    }

    gemm_tc<128, 0, true><<<gN, 256>>>(xcur, eW1, 128, eb1,
                                       up, 128, N_NODES, nullptr, nullptr);
    gemm_tc<128, 0, false><<<gN, 256>>>(xcur, eW1 + 128 * 128, 128, nullptr,
                                        wp, 128, N_NODES, nullptr, nullptr);
    edge_fused_kernel<<<N_EDGES / 16, 256>>>(up, wp, edges, edge_feats,
                                             eW1, eW2, eb2, eW3, eb3, out);
}

// round 4
// speedup vs baseline: 3.2461x; 1.2663x over previous
#include <cuda_runtime.h>
#include <cuda_bf16.h>
#include <cstdint>

#define N_NODES 50000
#define K_NBR   16
#define N_EDGES 200000
#define HID     128
#define NHEAD   4
#define FEAT    160
#define CTX     17

// ---------------- scratch ----------------
__device__ float g_feats[N_NODES * FEAT];
__device__ float g_xa[N_NODES * HID];
__device__ float g_xb[N_NODES * HID];
__device__ float g_qkv[N_NODES * 3 * HID];
__device__ float g_o[N_NODES * HID];
__device__ int   g_has[N_NODES];
__device__ float g_u[N_NODES * HID];
__device__ float g_w[N_NODES * HID];

// packed bf16x2 weights: [col][k/2]
// proj: 128*80 ; qkv: 3*384*64 ; wo: 3*128*64 ; u: 128*64 ; w: 128*64
#define WPK_PROJ 0
#define WPK_QKV  10240
#define WPK_WO   (WPK_QKV + 3 * 384 * 64)
#define WPK_U    (WPK_WO + 3 * 128 * 64)
#define WPK_W    (WPK_U + 128 * 64)
#define WPK_TOT  (WPK_W + 128 * 64)
__device__ uint32_t g_wpk[WPK_TOT];

__device__ __forceinline__ uint32_t packbf(float lo, float hi) {
    __nv_bfloat162 p = __floats2bfloat162_rn(lo, hi);   // x (=lo) in low 16 bits
    return *reinterpret_cast<uint32_t*>(&p);
}

__device__ __forceinline__ void mma_bf16(float c[4], const uint32_t a[4],
                                         uint32_t b0, uint32_t b1) {
    asm volatile(
        "mma.sync.aligned.m16n8k16.row.col.f32.bf16.bf16.f32 "
        "{%0,%1,%2,%3}, {%4,%5,%6,%7}, {%8,%9}, {%0,%1,%2,%3};\n"
        : "+f"(c[0]), "+f"(c[1]), "+f"(c[2]), "+f"(c[3])
        : "r"(a[0]), "r"(a[1]), "r"(a[2]), "r"(a[3]), "r"(b0), "r"(b1));
}

// ---------------- weight pack: src[k][col] (K x NC fp32) -> dst[col][k/2] bf16x2 ----------------
__global__ void pack_kernel(const float* __restrict__ src, uint32_t* __restrict__ dst,
                            int K, int NC)
{
    int K2 = K >> 1;
    src += (size_t)blockIdx.y * K * NC;
    dst += (size_t)blockIdx.y * NC * K2;
    int i = blockIdx.x * blockDim.x + threadIdx.x;
    if (i >= NC * K2) return;
    int col = i / K2, kp = i - col * K2;
    float lo = src[(size_t)(2 * kp) * NC + col];
    float hi = src[(size_t)(2 * kp + 1) * NC + col];
    dst[(size_t)col * K2 + kp] = packbf(lo, hi);
}

// ---------------- node feature encoding ----------------
__global__ void encode_kernel(const int* __restrict__ type_idx,
                              const int* __restrict__ cat_idx,
                              const float* __restrict__ log_deg,
                              const float* __restrict__ type_embed,
                              const float* __restrict__ cat_embed0,
                              const float* __restrict__ cat_embed1,
                              const float* __restrict__ deg_W,
                              const float* __restrict__ deg_b,
                              float* __restrict__ feats)
{
    int i = blockIdx.x * blockDim.x + threadIdx.x;
    if (i >= N_NODES * FEAT) return;
    int n = i / FEAT, j = i - n * FEAT;
    float v;
    if (j < 64)        v = type_embed[type_idx[n] * 64 + j];
    else if (j < 96)   v = cat_embed0[cat_idx[2 * n] * 32 + (j - 64)];
    else if (j < 128)  v = cat_embed1[cat_idx[2 * n + 1] * 32 + (j - 96)];
    else {
        int jj = j - 128;
        v = fmaxf(log_deg[n] * deg_W[jj] + deg_b[jj], 0.f);
    }
    feats[i] = v;
}

__global__ void hasnbr_kernel(const int* __restrict__ nbr_mask, int* __restrict__ has)
{
    int n = blockIdx.x * blockDim.x + threadIdx.x;
    if (n >= N_NODES) return;
    int a = 0;
#pragma unroll
    for (int j = 0; j < K_NBR; j++) a |= nbr_mask[n * K_NBR + j];
    has[n] = a ? 1 : 0;
}

// ---------------- bf16 tensor-core GEMM, 128x128 tile, one-shot full-K staging ----------------
// out[r, colbase+c] = sum_k A[r,k] * W[k, colbase+c] (+bias)
// Wpk: packed [col][k/2]. MODE 0: plain; MODE 2: relu(where(fbmask, val, fbx))
template <int KDIM, int MODE, bool HASBIAS>
__global__ void __launch_bounds__(256, 2)
gemm_bf16(const float* __restrict__ A, const uint32_t* __restrict__ Wpk,
          const float* __restrict__ bias, float* __restrict__ out, int ldo,
          int rows, const float* __restrict__ fbx, const int* __restrict__ fbmask)
{
    constexpr int K2  = KDIM / 2;
    constexpr int K2P = (KDIM == 160) ? 84 : 68;   // bank stride 20 / 4 -> frag LDS conflict-free
    constexpr int K4  = KDIM / 4;
    constexpr int KQ  = K2 / 4;

    extern __shared__ __align__(16) uint32_t dsm[];
    uint32_t* As = dsm;                  // [128][K2P]
    uint32_t* Bs = dsm + 128 * K2P;      // [128][K2P]

    int t = threadIdx.x, lane = t & 31, wid = t >> 5;
    int g = lane >> 2, tig = lane & 3;
    int wm = wid & 3, wn = wid >> 2;     // 4(m) x 2(n) warps, warp tile 32x64
    int row0 = blockIdx.x * 128;
    int colbase = blockIdx.y * 128;

    // stage A (fp32 -> packed bf16x2, row-major k-pairs)
#pragma unroll
    for (int it = 0; it < 128 * K4 / 256; it++) {
        int i = t + it * 256;
        int r = i / K4, c4 = (i - r * K4) * 4;
        int gr = row0 + r;
        float4 a = make_float4(0.f, 0.f, 0.f, 0.f);
        if (gr < rows) a = *reinterpret_cast<const float4*>(&A[(size_t)gr * KDIM + c4]);
        As[r * K2P + (c4 >> 1)]     = packbf(a.x, a.y);
        As[r * K2P + (c4 >> 1) + 1] = packbf(a.z, a.w);
    }
    // stage B (already packed; coalesced uint4 copy)
#pragma unroll
    for (int it = 0; it < 128 * KQ / 256; it++) {
        int i = t + it * 256;
        int c = i / KQ, kq = (i - c * KQ) * 4;
        uint4 v = *reinterpret_cast<const uint4*>(&Wpk[(size_t)(colbase + c) * K2 + kq]);
        *reinterpret_cast<uint4*>(&Bs[c * K2P + kq]) = v;
    }
    __syncthreads();

    float acc[2][8][4];
#pragma unroll
    for (int i = 0; i < 2; i++)
#pragma unroll
        for (int j = 0; j < 8; j++)
#pragma unroll
            for (int k = 0; k < 4; k++) acc[i][j][k] = 0.f;

#pragma unroll
    for (int s = 0; s < K2 / 8; s++) {
        int s8 = s * 8;
        uint32_t a[2][4];
#pragma unroll
        for (int mt = 0; mt < 2; mt++) {
            int rb = wm * 32 + mt * 16;
            a[mt][0] = As[(rb + g) * K2P + s8 + tig];
            a[mt][1] = As[(rb + g + 8) * K2P + s8 + tig];
            a[mt][2] = As[(rb + g) * K2P + s8 + tig + 4];
            a[mt][3] = As[(rb + g + 8) * K2P + s8 + tig + 4];
        }
#pragma unroll
        for (int nt = 0; nt < 8; nt++) {
            int cb = wn * 64 + nt * 8;
            uint32_t b0 = Bs[(cb + g) * K2P + s8 + tig];
            uint32_t b1 = Bs[(cb + g) * K2P + s8 + tig + 4];
            mma_bf16(acc[0][nt], a[0], b0, b1);
            mma_bf16(acc[1][nt], a[1], b0, b1);
        }
    }

    // epilogue (C frag: c0,c1 row g, cols tig*2..+1; c2,c3 row g+8)
#pragma unroll
    for (int mt = 0; mt < 2; mt++) {
#pragma unroll
        for (int half = 0; half < 2; half++) {
            int gr = row0 + wm * 32 + mt * 16 + g + half * 8;
            if (gr >= rows) continue;
            bool fb = false;
            if (MODE == 2) fb = (fbmask[gr] == 0);
#pragma unroll
            for (int nt = 0; nt < 8; nt++) {
                int col = colbase + wn * 64 + nt * 8 + tig * 2;
                float v0 = acc[mt][nt][half * 2 + 0];
                float v1 = acc[mt][nt][half * 2 + 1];
                if (HASBIAS) { v0 += bias[col]; v1 += bias[col + 1]; }
                if (MODE == 2) {
                    if (fb) {
                        float2 f = *reinterpret_cast<const float2*>(&fbx[(size_t)gr * HID + col]);
                        v0 = f.x; v1 = f.y;
                    }
                    v0 = fmaxf(v0, 0.f);
                    v1 = fmaxf(v1, 0.f);
                }
                *reinterpret_cast<float2*>(&out[(size_t)gr * ldo + col]) = make_float2(v0, v1);
            }
        }
    }
}

// ---------------- local-context attention: one warp per NODE (all 4 heads) ----------------
__global__ void attn_kernel(const float* __restrict__ qkv,
                            const int* __restrict__ nbr_idx,
                            const int* __restrict__ nbr_mask,
                            float* __restrict__ o)
{
    int n = (blockIdx.x * blockDim.x + threadIdx.x) >> 5;
    if (n >= N_NODES) return;
    int lane = threadIdx.x & 31;
    int off = lane * 4;

    float4 q = *reinterpret_cast<const float4*>(&qkv[(size_t)n * 384 + off]);

    int nb = 0, mk = 0;
    if (lane < 16) {
        nb = nbr_idx[n * K_NBR + lane];
        mk = nbr_mask[n * K_NBR + lane];
    }
    unsigned mb = __ballot_sync(0xffffffffu, (lane < 16) && mk);

    int idxs[CTX];
    float sc[CTX];
    idxs[0] = n;
#pragma unroll
    for (int c = 0; c < CTX; c++) {
        int id = (c == 0) ? n : __shfl_sync(0xffffffffu, nb, c - 1);
        idxs[c] = id;
        float4 k4 = *reinterpret_cast<const float4*>(&qkv[(size_t)id * 384 + 128 + off]);
        float s = q.x * k4.x + q.y * k4.y + q.z * k4.z + q.w * k4.w;
        s += __shfl_xor_sync(0xffffffffu, s, 4);
        s += __shfl_xor_sync(0xffffffffu, s, 2);
        s += __shfl_xor_sync(0xffffffffu, s, 1);
        s *= 0.17677669529663687f;
        if (c > 0 && !((mb >> (c - 1)) & 1)) s = -1e9f;
        sc[c] = s;
    }

    float mx = sc[0];
#pragma unroll
    for (int c = 1; c < CTX; c++) mx = fmaxf(mx, sc[c]);
    float den = 0.f;
#pragma unroll
    for (int c = 0; c < CTX; c++) { sc[c] = __expf(sc[c] - mx); den += sc[c]; }
    float inv = 1.f / den;

    float4 av = make_float4(0.f, 0.f, 0.f, 0.f);
#pragma unroll
    for (int c = 0; c < CTX; c++) {
        float4 v4 = *reinterpret_cast<const float4*>(&qkv[(size_t)idxs[c] * 384 + 256 + off]);
        float p = sc[c];
        av.x += p * v4.x; av.y += p * v4.y; av.z += p * v4.z; av.w += p * v4.w;
    }
    av.x *= inv; av.y *= inv; av.z *= inv; av.w *= inv;
    *reinterpret_cast<float4*>(&o[(size_t)n * HID + off]) = av;
}

// ---------------- fused edge MLP: 32 edges per block ----------------
__global__ void edge_fused_kernel(const float* __restrict__ u,
                                  const float* __restrict__ w,
                                  const int* __restrict__ edges,
                                  const float* __restrict__ ef,
                                  const float* __restrict__ eW1,
                                  const float* __restrict__ eW2,
                                  const float* __restrict__ eb2,
                                  const float* __restrict__ eW3,
                                  const float* __restrict__ eb3,
                                  float* __restrict__ out)
{
    extern __shared__ __align__(16) float dynf[];
    float (*W2t)[132] = reinterpret_cast<float(*)[132]>(dynf);          // 64 x 132
    float (*h1s)[128] = reinterpret_cast<float(*)[128]>(dynf + 64 * 132); // 32 x 128
    float* W3s = dynf + 64 * 132 + 32 * 128;
    float* b2s = W3s + 64;

    int t = threadIdx.x;
    int lane = t & 31, wid = t >> 5;
    int e0 = blockIdx.x * 32;

    // stage eW2 transposed
#pragma unroll
    for (int it = 0; it < 8; it++) {
        int fidx = t + it * 256;
        int j = fidx >> 4, c4 = (fidx & 15) << 2;
        float4 v = *reinterpret_cast<const float4*>(&eW2[(size_t)j * 64 + c4]);
        W2t[c4 + 0][j] = v.x;
        W2t[c4 + 1][j] = v.y;
        W2t[c4 + 2][j] = v.z;
        W2t[c4 + 3][j] = v.w;
    }
    if (t < 64) { W3s[t] = eW3[t]; b2s[t] = eb2[t]; }

    const float* wef0 = eW1 + 256 * 128;
    const float* wef1 = eW1 + 257 * 128;
    float4 we0 = *reinterpret_cast<const float4*>(&wef0[lane * 4]);
    float4 we1 = *reinterpret_cast<const float4*>(&wef1[lane * 4]);

    // phase 1: h1 for this warp's 4 edges
#pragma unroll
    for (int ee = 0; ee < 4; ee++) {
        int el = wid * 4 + ee;
        int e = e0 + el;
        int s = edges[2 * e], d = edges[2 * e + 1];
        float f0 = ef[2 * e], f1 = ef[2 * e + 1];
        float4 uu = *reinterpret_cast<const float4*>(&u[(size_t)s * HID + lane * 4]);
        float4 ww = *reinterpret_cast<const float4*>(&w[(size_t)d * HID + lane * 4]);
        float4 h;
        h.x = fmaxf(uu.x + ww.x + f0 * we0.x + f1 * we1.x, 0.f);
        h.y = fmaxf(uu.y + ww.y + f0 * we0.y + f1 * we1.y, 0.f);
        h.z = fmaxf(uu.z + ww.z + f0 * we0.z + f1 * we1.z, 0.f);
        h.w = fmaxf(uu.w + ww.w + f0 * we0.w + f1 * we1.w, 0.f);
        *reinterpret_cast<float4*>(&h1s[el][lane * 4]) = h;
    }
    __syncthreads();

    // phase 2: h2 cols (lane, lane+32) for 4 edges, then logit
    float acc[4][2] = {};
#pragma unroll 4
    for (int j4 = 0; j4 < 128; j4 += 4) {
        float4 w0 = *reinterpret_cast<const float4*>(&W2t[lane][j4]);
        float4 w1 = *reinterpret_cast<const float4*>(&W2t[lane + 32][j4]);
#pragma unroll
        for (int ee = 0; ee < 4; ee++) {
            float4 h = *reinterpret_cast<const float4*>(&h1s[wid * 4 + ee][j4]);
            acc[ee][0] += h.x * w0.x + h.y * w0.y + h.z * w0.z + h.w * w0.w;
            acc[ee][1] += h.x * w1.x + h.y * w1.y + h.z * w1.z + h.w * w1.w;
        }
    }
    float b0 = b2s[lane], b1 = b2s[lane + 32];
    float w3a = W3s[lane], w3b = W3s[lane + 32];

#pragma unroll
    for (int ee = 0; ee < 4; ee++) {
        float p = fmaxf(acc[ee][0] + b0, 0.f) * w3a + fmaxf(acc[ee][1] + b1, 0.f) * w3b;
        p += __shfl_xor_sync(0xffffffffu, p, 16);
        p += __shfl_xor_sync(0xffffffffu, p, 8);
        p += __shfl_xor_sync(0xffffffffu, p, 4);
        p += __shfl_xor_sync(0xffffffffu, p, 2);
        p += __shfl_xor_sync(0xffffffffu, p, 1);
        if (lane == 0) out[e0 + wid * 4 + ee] = p + eb3[0];
    }
}

// ---------------- launch ----------------
extern "C" void kernel_launch(void* const* d_in, const int* in_sizes, int n_in,
                              void* d_out, int out_size)
{
    (void)in_sizes; (void)n_in; (void)out_size;
    const int*   type_idx   = (const int*)d_in[0];
    const int*   cat_idx    = (const int*)d_in[1];
    const int*   nbr_idx    = (const int*)d_in[2];
    const int*   nbr_mask   = (const int*)d_in[3];
    const int*   edges      = (const int*)d_in[4];
    const float* log_deg    = (const float*)d_in[5];
    const float* edge_feats = (const float*)d_in[6];
    const float* type_embed = (const float*)d_in[7];
    const float* cat_embed0 = (const float*)d_in[8];
    const float* cat_embed1 = (const float*)d_in[9];
    const float* deg_W      = (const float*)d_in[10];
    const float* deg_b      = (const float*)d_in[11];
    const float* proj_W     = (const float*)d_in[12];
    const float* proj_b     = (const float*)d_in[13];
    const float* Wqkv       = (const float*)d_in[14];
    const float* bqkv       = (const float*)d_in[15];
    const float* Wo         = (const float*)d_in[16];
    const float* bo         = (const float*)d_in[17];
    const float* eW1        = (const float*)d_in[18];
    const float* eb1        = (const float*)d_in[19];
    const float* eW2        = (const float*)d_in[20];
    const float* eb2        = (const float*)d_in[21];
    const float* eW3        = (const float*)d_in[22];
    const float* eb3        = (const float*)d_in[23];
    float* out = (float*)d_out;

    float *feats, *xa, *xb, *qkvp, *op, *up, *wp; int* has; uint32_t* wpk;
    cudaGetSymbolAddress((void**)&feats, g_feats);
    cudaGetSymbolAddress((void**)&xa, g_xa);
    cudaGetSymbolAddress((void**)&xb, g_xb);
    cudaGetSymbolAddress((void**)&qkvp, g_qkv);
    cudaGetSymbolAddress((void**)&op, g_o);
    cudaGetSymbolAddress((void**)&up, g_u);
    cudaGetSymbolAddress((void**)&wp, g_w);
    cudaGetSymbolAddress((void**)&has, g_has);
    cudaGetSymbolAddress((void**)&wpk, g_wpk);

    const int SM128 = 2 * 128 * 68 * 4;   // 69632
    const int SM160 = 2 * 128 * 84 * 4;   // 86016
    const int SMEDGE = (64 * 132 + 32 * 128 + 128) * 4;  // 50688
    cudaFuncSetAttribute(gemm_bf16<160, 0, true>, cudaFuncAttributeMaxDynamicSharedMemorySize, SM160);
    cudaFuncSetAttribute(gemm_bf16<128, 0, true>, cudaFuncAttributeMaxDynamicSharedMemorySize, SM128);
    cudaFuncSetAttribute(gemm_bf16<128, 2, true>, cudaFuncAttributeMaxDynamicSharedMemorySize, SM128);
    cudaFuncSetAttribute(gemm_bf16<128, 0, false>, cudaFuncAttributeMaxDynamicSharedMemorySize, SM128);
    cudaFuncSetAttribute(edge_fused_kernel, cudaFuncAttributeMaxDynamicSharedMemorySize, SMEDGE);

    // ---- weight packing ----
    pack_kernel<<<dim3((128 * 80 + 255) / 256, 1), 256>>>(proj_W, wpk + WPK_PROJ, 160, 128);
    pack_kernel<<<dim3((384 * 64 + 255) / 256, 3), 256>>>(Wqkv, wpk + WPK_QKV, 128, 384);
    pack_kernel<<<dim3((128 * 64 + 255) / 256, 3), 256>>>(Wo, wpk + WPK_WO, 128, 128);
    pack_kernel<<<dim3((128 * 64 + 255) / 256, 1), 256>>>(eW1, wpk + WPK_U, 128, 128);
    pack_kernel<<<dim3((128 * 64 + 255) / 256, 1), 256>>>(eW1 + 128 * 128, wpk + WPK_W, 128, 128);

    encode_kernel<<<(N_NODES * FEAT + 255) / 256, 256>>>(
        type_idx, cat_idx, log_deg, type_embed, cat_embed0, cat_embed1, deg_W, deg_b, feats);
    hasnbr_kernel<<<(N_NODES + 255) / 256, 256>>>(nbr_mask, has);

    int gN = (N_NODES + 127) / 128;   // 391
    gemm_bf16<160, 0, true><<<gN, 256, SM160>>>(feats, wpk + WPK_PROJ, proj_b,
                                                xa, 128, N_NODES, nullptr, nullptr);

    float* xcur = xa;
    float* xnxt = xb;
    for (int l = 0; l < 3; l++) {
        gemm_bf16<128, 0, true><<<dim3(gN, 3), 256, SM128>>>(
            xcur, wpk + WPK_QKV + l * 384 * 64, bqkv + (size_t)l * 384,
            qkvp, 384, N_NODES, nullptr, nullptr);
        attn_kernel<<<(N_NODES + 7) / 8, 256>>>(qkvp, nbr_idx, nbr_mask, op);
        gemm_bf16<128, 2, true><<<gN, 256, SM128>>>(
            op, wpk + WPK_WO + l * 128 * 64, bo + (size_t)l * 128,
            xnxt, 128, N_NODES, xcur, has);
        float* tmp = xcur; xcur = xnxt; xnxt = tmp;
    }

    gemm_bf16<128, 0, true><<<gN, 256, SM128>>>(xcur, wpk + WPK_U, eb1,
                                                up, 128, N_NODES, nullptr, nullptr);
    gemm_bf16<128, 0, false><<<gN, 256, SM128>>>(xcur, wpk + WPK_W, nullptr,
                                                 wp, 128, N_NODES, nullptr, nullptr);
    edge_fused_kernel<<<N_EDGES / 32, 256, SMEDGE>>>(up, wp, edges, edge_feats,
                                                     eW1, eW2, eb2, eW3, eb3, out);
}

// round 5
// speedup vs baseline: 3.7733x; 1.1624x over previous
#include <cuda_runtime.h>
#include <cuda_bf16.h>
#include <cstdint>

#define N_NODES 50000
#define K_NBR   16
#define N_EDGES 200000
#define HID     128
#define FEAT    160
#define CTX     17

// ---------------- scratch ----------------
__device__ float    g_feats[N_NODES * FEAT];
__device__ float    g_xa[N_NODES * HID];
__device__ float    g_xb[N_NODES * HID];
__device__ uint32_t g_qkvb[N_NODES * 192];     // qkv packed bf16x2: [n][192]
__device__ float    g_o[N_NODES * HID];
__device__ int      g_has[N_NODES];
__device__ uint32_t g_uwb[N_NODES * 128];      // [u(64) | w(64)] packed bf16x2 per node
__device__ float    g_biasuw[256];

// packed bf16x2 weights: [col][k/2]
#define WPK_PROJ 0
#define WPK_QKV  10240
#define WPK_WO   (WPK_QKV + 3 * 384 * 64)
#define WPK_UW   (WPK_WO + 3 * 128 * 64)
#define WPK_TOT  (WPK_UW + 2 * 128 * 64)
__device__ uint32_t g_wpk[WPK_TOT];

__device__ __forceinline__ uint32_t packbf(float lo, float hi) {
    __nv_bfloat162 p = __floats2bfloat162_rn(lo, hi);
    return *reinterpret_cast<uint32_t*>(&p);
}
__device__ __forceinline__ float2 unpk(uint32_t u) {
    __nv_bfloat162 b = *reinterpret_cast<__nv_bfloat162*>(&u);
    return __bfloat1622float2(b);
}

__device__ __forceinline__ void mma_bf16(float c[4], const uint32_t a[4],
                                         uint32_t b0, uint32_t b1) {
    asm volatile(
        "mma.sync.aligned.m16n8k16.row.col.f32.bf16.bf16.f32 "
        "{%0,%1,%2,%3}, {%4,%5,%6,%7}, {%8,%9}, {%0,%1,%2,%3};\n"
        : "+f"(c[0]), "+f"(c[1]), "+f"(c[2]), "+f"(c[3])
        : "r"(a[0]), "r"(a[1]), "r"(a[2]), "r"(a[3]), "r"(b0), "r"(b1));
}

// ---------------- mega pack: all weights -> packed bf16x2, plus combined u/w bias ----------------
// src[k][col] -> dst[col][k/2]
__global__ void pack_all_kernel(const float* __restrict__ proj_W,
                                const float* __restrict__ Wqkv,
                                const float* __restrict__ Wo,
                                const float* __restrict__ eW1,
                                const float* __restrict__ eb1,
                                uint32_t* __restrict__ wpk,
                                float* __restrict__ biasuw)
{
    int i = blockIdx.x * blockDim.x + threadIdx.x;
    if (i < 10240) {                                   // proj: K=160, NC=128
        int col = i / 80, kp = i - col * 80;
        wpk[WPK_PROJ + i] = packbf(proj_W[(size_t)(2 * kp) * 128 + col],
                                   proj_W[(size_t)(2 * kp + 1) * 128 + col]);
        return;
    }
    i -= 10240;
    if (i < 73728) {                                   // qkv: 3 x (K=128, NC=384)
        int l = i / 24576, r = i - l * 24576;
        int col = r / 64, kp = r - col * 64;
        const float* s = Wqkv + (size_t)l * 128 * 384;
        wpk[WPK_QKV + i] = packbf(s[(size_t)(2 * kp) * 384 + col],
                                  s[(size_t)(2 * kp + 1) * 384 + col]);
        return;
    }
    i -= 73728;
    if (i < 24576) {                                   // wo: 3 x (K=128, NC=128)
        int l = i / 8192, r = i - l * 8192;
        int col = r / 64, kp = r - col * 64;
        const float* s = Wo + (size_t)l * 128 * 128;
        wpk[WPK_WO + i] = packbf(s[(size_t)(2 * kp) * 128 + col],
                                 s[(size_t)(2 * kp + 1) * 128 + col]);
        return;
    }
    i -= 24576;
    if (i < 16384) {                                   // u/w: eW1 rows 0-127 and 128-255
        int seg = i >> 13, r = i & 8191;
        int col = r / 64, kp = r - col * 64;
        const float* s = eW1 + (size_t)seg * 128 * 128;
        wpk[WPK_UW + i] = packbf(s[(size_t)(2 * kp) * 128 + col],
                                 s[(size_t)(2 * kp + 1) * 128 + col]);
        return;
    }
    i -= 16384;
    if (i < 256) biasuw[i] = (i < 128) ? eb1[i] : 0.f;
}

// ---------------- node feature encoding + has_nbr (fused) ----------------
__global__ void encode_kernel(const int* __restrict__ type_idx,
                              const int* __restrict__ cat_idx,
                              const float* __restrict__ log_deg,
                              const float* __restrict__ type_embed,
                              const float* __restrict__ cat_embed0,
                              const float* __restrict__ cat_embed1,
                              const float* __restrict__ deg_W,
                              const float* __restrict__ deg_b,
                              const int* __restrict__ nbr_mask,
                              float* __restrict__ feats,
                              int* __restrict__ has)
{
    int i = blockIdx.x * blockDim.x + threadIdx.x;
    if (i < N_NODES * FEAT) {
        int n = i / FEAT, j = i - n * FEAT;
        float v;
        if (j < 64)        v = type_embed[type_idx[n] * 64 + j];
        else if (j < 96)   v = cat_embed0[cat_idx[2 * n] * 32 + (j - 64)];
        else if (j < 128)  v = cat_embed1[cat_idx[2 * n + 1] * 32 + (j - 96)];
        else {
            int jj = j - 128;
            v = fmaxf(log_deg[n] * deg_W[jj] + deg_b[jj], 0.f);
        }
        feats[i] = v;
        return;
    }
    int n = i - N_NODES * FEAT;
    if (n < N_NODES) {
        int a = 0;
#pragma unroll
        for (int j = 0; j < K_NBR; j++) a |= nbr_mask[n * K_NBR + j];
        has[n] = a ? 1 : 0;
    }
}

// ---------------- bf16 tensor-core GEMM, 128x128 tile, full-K one-shot staging ----------------
// MODE 0: plain; MODE 2: relu(where(fbmask, val, fbx)).  OUTBF: pack output pairs to bf16x2.
// ldo: element stride (floats for OUTBF=0, uint32-pairs for OUTBF=1)
template <int KDIM, int MODE, bool HASBIAS, bool OUTBF>
__global__ void __launch_bounds__(256, 2)
gemm_bf16(const float* __restrict__ A, const uint32_t* __restrict__ Wpk,
          const float* __restrict__ bias, void* __restrict__ outv, int ldo,
          int rows, const float* __restrict__ fbx, const int* __restrict__ fbmask)
{
    constexpr int K2  = KDIM / 2;
    constexpr int K2P = (KDIM == 160) ? 84 : 68;
    constexpr int K4  = KDIM / 4;
    constexpr int KQ  = K2 / 4;

    extern __shared__ __align__(16) uint32_t dsm[];
    uint32_t* As = dsm;                  // [128][K2P]
    uint32_t* Bs = dsm + 128 * K2P;      // [128][K2P]

    int t = threadIdx.x, lane = t & 31, wid = t >> 5;
    int g = lane >> 2, tig = lane & 3;
    int wm = wid & 3, wn = wid >> 2;
    int row0 = blockIdx.x * 128;
    int colbase = blockIdx.y * 128;

#pragma unroll
    for (int it = 0; it < 128 * K4 / 256; it++) {
        int i = t + it * 256;
        int r = i / K4, c4 = (i - r * K4) * 4;
        int gr = row0 + r;
        float4 a = make_float4(0.f, 0.f, 0.f, 0.f);
        if (gr < rows) a = *reinterpret_cast<const float4*>(&A[(size_t)gr * KDIM + c4]);
        As[r * K2P + (c4 >> 1)]     = packbf(a.x, a.y);
        As[r * K2P + (c4 >> 1) + 1] = packbf(a.z, a.w);
    }
#pragma unroll
    for (int it = 0; it < 128 * KQ / 256; it++) {
        int i = t + it * 256;
        int c = i / KQ, kq = (i - c * KQ) * 4;
        uint4 v = *reinterpret_cast<const uint4*>(&Wpk[(size_t)(colbase + c) * K2 + kq]);
        *reinterpret_cast<uint4*>(&Bs[c * K2P + kq]) = v;
    }
    __syncthreads();

    float acc[2][8][4];
#pragma unroll
    for (int i = 0; i < 2; i++)
#pragma unroll
        for (int j = 0; j < 8; j++)
#pragma unroll
            for (int k = 0; k < 4; k++) acc[i][j][k] = 0.f;

#pragma unroll
    for (int s = 0; s < K2 / 8; s++) {
        int s8 = s * 8;
        uint32_t a[2][4];
#pragma unroll
        for (int mt = 0; mt < 2; mt++) {
            int rb = wm * 32 + mt * 16;
            a[mt][0] = As[(rb + g) * K2P + s8 + tig];
            a[mt][1] = As[(rb + g + 8) * K2P + s8 + tig];
            a[mt][2] = As[(rb + g) * K2P + s8 + tig + 4];
            a[mt][3] = As[(rb + g + 8) * K2P + s8 + tig + 4];
        }
#pragma unroll
        for (int nt = 0; nt < 8; nt++) {
            int cb = wn * 64 + nt * 8;
            uint32_t b0 = Bs[(cb + g) * K2P + s8 + tig];
            uint32_t b1 = Bs[(cb + g) * K2P + s8 + tig + 4];
            mma_bf16(acc[0][nt], a[0], b0, b1);
            mma_bf16(acc[1][nt], a[1], b0, b1);
        }
    }

#pragma unroll
    for (int mt = 0; mt < 2; mt++) {
#pragma unroll
        for (int half = 0; half < 2; half++) {
            int gr = row0 + wm * 32 + mt * 16 + g + half * 8;
            if (gr >= rows) continue;
            bool fb = false;
            if (MODE == 2) fb = (fbmask[gr] == 0);
#pragma unroll
            for (int nt = 0; nt < 8; nt++) {
                int col = colbase + wn * 64 + nt * 8 + tig * 2;
                float v0 = acc[mt][nt][half * 2 + 0];
                float v1 = acc[mt][nt][half * 2 + 1];
                if (HASBIAS) { v0 += bias[col]; v1 += bias[col + 1]; }
                if (MODE == 2) {
                    if (fb) {
                        float2 f = *reinterpret_cast<const float2*>(&fbx[(size_t)gr * HID + col]);
                        v0 = f.x; v1 = f.y;
                    }
                    v0 = fmaxf(v0, 0.f);
                    v1 = fmaxf(v1, 0.f);
                }
                if (OUTBF) {
                    reinterpret_cast<uint32_t*>(outv)[(size_t)gr * ldo + (col >> 1)] =
                        packbf(v0, v1);
                } else {
                    *reinterpret_cast<float2*>(
                        &reinterpret_cast<float*>(outv)[(size_t)gr * ldo + col]) =
                        make_float2(v0, v1);
                }
            }
        }
    }
}

// ---------------- local-context attention on packed bf16 qkv: one warp per node ----------------
__global__ void attn_kernel(const uint32_t* __restrict__ qkvb,
                            const int* __restrict__ nbr_idx,
                            const int* __restrict__ nbr_mask,
                            float* __restrict__ o)
{
    int n = (blockIdx.x * blockDim.x + threadIdx.x) >> 5;
    if (n >= N_NODES) return;
    int lane = threadIdx.x & 31;
    int p2 = lane * 2;                    // uint32 pair offset for this lane's 4 dims

    uint2 qp = *reinterpret_cast<const uint2*>(&qkvb[(size_t)n * 192 + p2]);
    float2 qa = unpk(qp.x), qb = unpk(qp.y);

    int nb = 0, mk = 0;
    if (lane < 16) {
        nb = nbr_idx[n * K_NBR + lane];
        mk = nbr_mask[n * K_NBR + lane];
    }
    unsigned mb = __ballot_sync(0xffffffffu, (lane < 16) && mk);

    int idxs[CTX];
    float sc[CTX];
#pragma unroll
    for (int c = 0; c < CTX; c++) {
        int id = (c == 0) ? n : __shfl_sync(0xffffffffu, nb, c - 1);
        idxs[c] = id;
        uint2 kp = *reinterpret_cast<const uint2*>(&qkvb[(size_t)id * 192 + 64 + p2]);
        float2 ka = unpk(kp.x), kb = unpk(kp.y);
        float s = qa.x * ka.x + qa.y * ka.y + qb.x * kb.x + qb.y * kb.y;
        s += __shfl_xor_sync(0xffffffffu, s, 4);
        s += __shfl_xor_sync(0xffffffffu, s, 2);
        s += __shfl_xor_sync(0xffffffffu, s, 1);
        s *= 0.17677669529663687f;
        if (c > 0 && !((mb >> (c - 1)) & 1)) s = -1e9f;
        sc[c] = s;
    }

    float mx = sc[0];
#pragma unroll
    for (int c = 1; c < CTX; c++) mx = fmaxf(mx, sc[c]);
    float den = 0.f;
#pragma unroll
    for (int c = 0; c < CTX; c++) { sc[c] = __expf(sc[c] - mx); den += sc[c]; }
    float inv = 1.f / den;

    float4 av = make_float4(0.f, 0.f, 0.f, 0.f);
#pragma unroll
    for (int c = 0; c < CTX; c++) {
        uint2 vp = *reinterpret_cast<const uint2*>(&qkvb[(size_t)idxs[c] * 192 + 128 + p2]);
        float2 va = unpk(vp.x), vb = unpk(vp.y);
        float p = sc[c];
        av.x += p * va.x; av.y += p * va.y; av.z += p * vb.x; av.w += p * vb.y;
    }
    av.x *= inv; av.y *= inv; av.z *= inv; av.w *= inv;
    *reinterpret_cast<float4*>(&o[(size_t)n * HID + lane * 4]) = av;
}

// ---------------- fused edge MLP on packed bf16 u/w: 32 edges per block ----------------
__global__ void edge_fused_kernel(const uint32_t* __restrict__ uwb,
                                  const int* __restrict__ edges,
                                  const float* __restrict__ ef,
                                  const float* __restrict__ eW1,
                                  const float* __restrict__ eW2,
                                  const float* __restrict__ eb2,
                                  const float* __restrict__ eW3,
                                  const float* __restrict__ eb3,
                                  float* __restrict__ out)
{
    extern __shared__ __align__(16) float dynf[];
    float (*W2t)[132] = reinterpret_cast<float(*)[132]>(dynf);
    float (*h1s)[128] = reinterpret_cast<float(*)[128]>(dynf + 64 * 132);
    float* W3s = dynf + 64 * 132 + 32 * 128;
    float* b2s = W3s + 64;

    int t = threadIdx.x;
    int lane = t & 31, wid = t >> 5;
    int e0 = blockIdx.x * 32;

#pragma unroll
    for (int it = 0; it < 8; it++) {
        int fidx = t + it * 256;
        int j = fidx >> 4, c4 = (fidx & 15) << 2;
        float4 v = *reinterpret_cast<const float4*>(&eW2[(size_t)j * 64 + c4]);
        W2t[c4 + 0][j] = v.x;
        W2t[c4 + 1][j] = v.y;
        W2t[c4 + 2][j] = v.z;
        W2t[c4 + 3][j] = v.w;
    }
    if (t < 64) { W3s[t] = eW3[t]; b2s[t] = eb2[t]; }

    const float* wef0 = eW1 + 256 * 128;
    const float* wef1 = eW1 + 257 * 128;
    float4 we0 = *reinterpret_cast<const float4*>(&wef0[lane * 4]);
    float4 we1 = *reinterpret_cast<const float4*>(&wef1[lane * 4]);

#pragma unroll
    for (int ee = 0; ee < 4; ee++) {
        int el = wid * 4 + ee;
        int e = e0 + el;
        int s = edges[2 * e], d = edges[2 * e + 1];
        float f0 = ef[2 * e], f1 = ef[2 * e + 1];
        uint2 up2 = *reinterpret_cast<const uint2*>(&uwb[(size_t)s * 128 + lane * 2]);
        uint2 wp2 = *reinterpret_cast<const uint2*>(&uwb[(size_t)d * 128 + 64 + lane * 2]);
        float2 ua = unpk(up2.x), ub = unpk(up2.y);
        float2 wa = unpk(wp2.x), wb = unpk(wp2.y);
        float4 h;
        h.x = fmaxf(ua.x + wa.x + f0 * we0.x + f1 * we1.x, 0.f);
        h.y = fmaxf(ua.y + wa.y + f0 * we0.y + f1 * we1.y, 0.f);
        h.z = fmaxf(ub.x + wb.x + f0 * we0.z + f1 * we1.z, 0.f);
        h.w = fmaxf(ub.y + wb.y + f0 * we0.w + f1 * we1.w, 0.f);
        *reinterpret_cast<float4*>(&h1s[el][lane * 4]) = h;
    }
    __syncthreads();

    float acc[4][2] = {};
#pragma unroll 4
    for (int j4 = 0; j4 < 128; j4 += 4) {
        float4 w0 = *reinterpret_cast<const float4*>(&W2t[lane][j4]);
        float4 w1 = *reinterpret_cast<const float4*>(&W2t[lane + 32][j4]);
#pragma unroll
        for (int ee = 0; ee < 4; ee++) {
            float4 h = *reinterpret_cast<const float4*>(&h1s[wid * 4 + ee][j4]);
            acc[ee][0] += h.x * w0.x + h.y * w0.y + h.z * w0.z + h.w * w0.w;
            acc[ee][1] += h.x * w1.x + h.y * w1.y + h.z * w1.z + h.w * w1.w;
        }
    }
    float b0 = b2s[lane], b1 = b2s[lane + 32];
    float w3a = W3s[lane], w3b = W3s[lane + 32];

#pragma unroll
    for (int ee = 0; ee < 4; ee++) {
        float p = fmaxf(acc[ee][0] + b0, 0.f) * w3a + fmaxf(acc[ee][1] + b1, 0.f) * w3b;
        p += __shfl_xor_sync(0xffffffffu, p, 16);
        p += __shfl_xor_sync(0xffffffffu, p, 8);
        p += __shfl_xor_sync(0xffffffffu, p, 4);
        p += __shfl_xor_sync(0xffffffffu, p, 2);
        p += __shfl_xor_sync(0xffffffffu, p, 1);
        if (lane == 0) out[e0 + wid * 4 + ee] = p + eb3[0];
    }
}

// ---------------- launch ----------------
extern "C" void kernel_launch(void* const* d_in, const int* in_sizes, int n_in,
                              void* d_out, int out_size)
{
    (void)in_sizes; (void)n_in; (void)out_size;
    const int*   type_idx   = (const int*)d_in[0];
    const int*   cat_idx    = (const int*)d_in[1];
    const int*   nbr_idx    = (const int*)d_in[2];
    const int*   nbr_mask   = (const int*)d_in[3];
    const int*   edges      = (const int*)d_in[4];
    const float* log_deg    = (const float*)d_in[5];
    const float* edge_feats = (const float*)d_in[6];
    const float* type_embed = (const float*)d_in[7];
    const float* cat_embed0 = (const float*)d_in[8];
    const float* cat_embed1 = (const float*)d_in[9];
    const float* deg_W      = (const float*)d_in[10];
    const float* deg_b      = (const float*)d_in[11];
    const float* proj_W     = (const float*)d_in[12];
    const float* proj_b     = (const float*)d_in[13];
    const float* Wqkv       = (const float*)d_in[14];
    const float* bqkv       = (const float*)d_in[15];
    const float* Wo         = (const float*)d_in[16];
    const float* bo         = (const float*)d_in[17];
    const float* eW1        = (const float*)d_in[18];
    const float* eb1        = (const float*)d_in[19];
    const float* eW2        = (const float*)d_in[20];
    const float* eb2        = (const float*)d_in[21];
    const float* eW3        = (const float*)d_in[22];
    const float* eb3        = (const float*)d_in[23];
    float* out = (float*)d_out;

    float *feats, *xa, *xb, *op, *biasuw; int* has; uint32_t *wpk, *qkvb, *uwb;
    cudaGetSymbolAddress((void**)&feats, g_feats);
    cudaGetSymbolAddress((void**)&xa, g_xa);
    cudaGetSymbolAddress((void**)&xb, g_xb);
    cudaGetSymbolAddress((void**)&qkvb, g_qkvb);
    cudaGetSymbolAddress((void**)&op, g_o);
    cudaGetSymbolAddress((void**)&uwb, g_uwb);
    cudaGetSymbolAddress((void**)&has, g_has);
    cudaGetSymbolAddress((void**)&wpk, g_wpk);
    cudaGetSymbolAddress((void**)&biasuw, g_biasuw);

    const int SM128 = 2 * 128 * 68 * 4;
    const int SM160 = 2 * 128 * 84 * 4;
    const int SMEDGE = (64 * 132 + 32 * 128 + 128) * 4;
    cudaFuncSetAttribute(gemm_bf16<160, 0, true, false>, cudaFuncAttributeMaxDynamicSharedMemorySize, SM160);
    cudaFuncSetAttribute(gemm_bf16<128, 0, true, true>, cudaFuncAttributeMaxDynamicSharedMemorySize, SM128);
    cudaFuncSetAttribute(gemm_bf16<128, 2, true, false>, cudaFuncAttributeMaxDynamicSharedMemorySize, SM128);
    cudaFuncSetAttribute(edge_fused_kernel, cudaFuncAttributeMaxDynamicSharedMemorySize, SMEDGE);

    pack_all_kernel<<<(125184 + 255) / 256, 256>>>(proj_W, Wqkv, Wo, eW1, eb1, wpk, biasuw);
    encode_kernel<<<(N_NODES * FEAT + N_NODES + 255) / 256, 256>>>(
        type_idx, cat_idx, log_deg, type_embed, cat_embed0, cat_embed1,
        deg_W, deg_b, nbr_mask, feats, has);

    int gN = (N_NODES + 127) / 128;
    gemm_bf16<160, 0, true, false><<<gN, 256, SM160>>>(
        feats, wpk + WPK_PROJ, proj_b, xa, 128, N_NODES, nullptr, nullptr);

    float* xcur = xa;
    float* xnxt = xb;
    for (int l = 0; l < 3; l++) {
        gemm_bf16<128, 0, true, true><<<dim3(gN, 3), 256, SM128>>>(
            xcur, wpk + WPK_QKV + l * 384 * 64, bqkv + (size_t)l * 384,
            qkvb, 192, N_NODES, nullptr, nullptr);
        attn_kernel<<<(N_NODES + 7) / 8, 256>>>(qkvb, nbr_idx, nbr_mask, op);
        gemm_bf16<128, 2, true, false><<<gN, 256, SM128>>>(
            op, wpk + WPK_WO + l * 128 * 64, bo + (size_t)l * 128,
            xnxt, 128, N_NODES, xcur, has);
        float* tmp = xcur; xcur = xnxt; xnxt = tmp;
    }

    // combined u/w GEMM: cols 0-127 = u (+eb1), 128-255 = w (+0)
    gemm_bf16<128, 0, true, true><<<dim3(gN, 2), 256, SM128>>>(
        xcur, wpk + WPK_UW, biasuw, uwb, 128, N_NODES, nullptr, nullptr);

    edge_fused_kernel<<<N_EDGES / 32, 256, SMEDGE>>>(
        uwb, edges, edge_feats, eW1, eW2, eb2, eW3, eb3, out);
}

// round 7
// speedup vs baseline: 5.1540x; 1.3659x over previous
#include <cuda_runtime.h>
#include <cuda_bf16.h>
#include <cstdint>

#define N_NODES 50000
#define K_NBR   16
#define N_EDGES 200000
#define HID     128
#define FEAT    160
#define CTX     17

// ---------------- scratch (activations packed bf16x2) ----------------
__device__ uint32_t g_featsb[N_NODES * 80];
__device__ uint32_t g_xab[N_NODES * 64];
__device__ uint32_t g_xbb[N_NODES * 64];
__device__ uint32_t g_qkvb[N_NODES * 192];
__device__ uint32_t g_ob[N_NODES * 64];
__device__ int      g_has[N_NODES];
__device__ uint32_t g_uwb[N_NODES * 128];      // [u(64) | w(64)] pairs
__device__ float    g_biasuw[256];

// packed bf16x2 weights [col][k/2]
#define WPK_PROJ 0
#define WPK_QKV  10240
#define WPK_WO   (WPK_QKV + 73728)
#define WPK_UW   (WPK_WO + 24576)
#define WPK_TOT  (WPK_UW + 16384)
__device__ uint32_t g_wpk[WPK_TOT];

__device__ __forceinline__ uint32_t packbf(float lo, float hi) {
    __nv_bfloat162 p = __floats2bfloat162_rn(lo, hi);
    return *reinterpret_cast<uint32_t*>(&p);
}
__device__ __forceinline__ float2 unpk(uint32_t u) {
    __nv_bfloat162 b = *reinterpret_cast<__nv_bfloat162*>(&u);
    return __bfloat1622float2(b);
}
__device__ __forceinline__ float to_tf32(float x) {
    uint32_t u;
    asm("cvt.rna.tf32.f32 %0, %1;" : "=r"(u) : "f"(x));
    return __uint_as_float(u);
}
__device__ __forceinline__ uint32_t smaddr(const void* p) {
    return (uint32_t)__cvta_generic_to_shared(p);
}
__device__ __forceinline__ void ldsm_x4(uint32_t& a0, uint32_t& a1, uint32_t& a2,
                                        uint32_t& a3, uint32_t addr) {
    asm volatile("ldmatrix.sync.aligned.m8n8.x4.shared.b16 {%0,%1,%2,%3}, [%4];"
                 : "=r"(a0), "=r"(a1), "=r"(a2), "=r"(a3) : "r"(addr));
}
__device__ __forceinline__ void ldsm_x2(uint32_t& b0, uint32_t& b1, uint32_t addr) {
    asm volatile("ldmatrix.sync.aligned.m8n8.x2.shared.b16 {%0,%1}, [%2];"
                 : "=r"(b0), "=r"(b1) : "r"(addr));
}
__device__ __forceinline__ void mma_bf16(float c[4], const uint32_t a[4],
                                         uint32_t b0, uint32_t b1) {
    asm volatile(
        "mma.sync.aligned.m16n8k16.row.col.f32.bf16.bf16.f32 "
        "{%0,%1,%2,%3}, {%4,%5,%6,%7}, {%8,%9}, {%0,%1,%2,%3};\n"
        : "+f"(c[0]), "+f"(c[1]), "+f"(c[2]), "+f"(c[3])
        : "r"(a[0]), "r"(a[1]), "r"(a[2]), "r"(a[3]), "r"(b0), "r"(b1));
}
__device__ __forceinline__ void mma_tf32(float c[4], const uint32_t a[4],
                                         uint32_t b0, uint32_t b1) {
    asm volatile(
        "mma.sync.aligned.m16n8k8.row.col.f32.tf32.tf32.f32 "
        "{%0,%1,%2,%3}, {%4,%5,%6,%7}, {%8,%9}, {%0,%1,%2,%3};\n"
        : "+f"(c[0]), "+f"(c[1]), "+f"(c[2]), "+f"(c[3])
        : "r"(a[0]), "r"(a[1]), "r"(a[2]), "r"(a[3]), "r"(b0), "r"(b1));
}

// ---------------- mega pack ----------------
__global__ void pack_all_kernel(const float* __restrict__ proj_W,
                                const float* __restrict__ Wqkv,
                                const float* __restrict__ Wo,
                                const float* __restrict__ eW1,
                                const float* __restrict__ eb1,
                                uint32_t* __restrict__ wpk,
                                float* __restrict__ biasuw)
{
    int i = blockIdx.x * blockDim.x + threadIdx.x;
    if (i < 10240) {                                   // proj: K=160, NC=128
        int col = i / 80, kp = i - col * 80;
        wpk[WPK_PROJ + i] = packbf(proj_W[(size_t)(2 * kp) * 128 + col],
                                   proj_W[(size_t)(2 * kp + 1) * 128 + col]);
        return;
    }
    i -= 10240;
    if (i < 73728) {                                   // qkv: 3 x (K=128, NC=384)
        int l = i / 24576, r = i - l * 24576;
        int col = r / 64, kp = r - col * 64;
        const float* s = Wqkv + (size_t)l * 128 * 384;
        wpk[WPK_QKV + i] = packbf(s[(size_t)(2 * kp) * 384 + col],
                                  s[(size_t)(2 * kp + 1) * 384 + col]);
        return;
    }
    i -= 73728;
    if (i < 24576) {                                   // wo: 3 x (K=128, NC=128)
        int l = i / 8192, r = i - l * 8192;
        int col = r / 64, kp = r - col * 64;
        const float* s = Wo + (size_t)l * 128 * 128;
        wpk[WPK_WO + i] = packbf(s[(size_t)(2 * kp) * 128 + col],
                                 s[(size_t)(2 * kp + 1) * 128 + col]);
        return;
    }
    i -= 24576;
    if (i < 16384) {                                   // u/w: eW1 rows 0-127, 128-255
        int seg = i >> 13, r = i & 8191;
        int col = r / 64, kp = r - col * 64;
        const float* s = eW1 + (size_t)seg * 128 * 128;
        wpk[WPK_UW + i] = packbf(s[(size_t)(2 * kp) * 128 + col],
                                 s[(size_t)(2 * kp + 1) * 128 + col]);
        return;
    }
    i -= 16384;
    if (i < 256) biasuw[i] = (i < 128) ? eb1[i] : 0.f;
}

// ---------------- node feature encoding (packed) + has_nbr ----------------
__global__ void encode_kernel(const int* __restrict__ type_idx,
                              const int* __restrict__ cat_idx,
                              const float* __restrict__ log_deg,
                              const float* __restrict__ type_embed,
                              const float* __restrict__ cat_embed0,
                              const float* __restrict__ cat_embed1,
                              const float* __restrict__ deg_W,
                              const float* __restrict__ deg_b,
                              const int* __restrict__ nbr_mask,
                              uint32_t* __restrict__ featsb,
                              int* __restrict__ has)
{
    int i = blockIdx.x * blockDim.x + threadIdx.x;
    if (i < N_NODES * 80) {
        int n = i / 80, jp = i - n * 80;
        int j = jp * 2;
        float lo, hi;
        if (j < 64) {
            const float* e = type_embed + type_idx[n] * 64 + j;
            lo = e[0]; hi = e[1];
        } else if (j < 96) {
            const float* e = cat_embed0 + cat_idx[2 * n] * 32 + (j - 64);
            lo = e[0]; hi = e[1];
        } else if (j < 128) {
            const float* e = cat_embed1 + cat_idx[2 * n + 1] * 32 + (j - 96);
            lo = e[0]; hi = e[1];
        } else {
            int jj = j - 128;
            float d = log_deg[n];
            lo = fmaxf(d * deg_W[jj] + deg_b[jj], 0.f);
            hi = fmaxf(d * deg_W[jj + 1] + deg_b[jj + 1], 0.f);
        }
        featsb[i] = packbf(lo, hi);
        return;
    }
    int n = i - N_NODES * 80;
    if (n < N_NODES) {
        int a = 0;
#pragma unroll
        for (int j = 0; j < K_NBR; j++) a |= nbr_mask[n * K_NBR + j];
        has[n] = a ? 1 : 0;
    }
}

// ---------------- bf16 TC GEMM, packed in/out, ldmatrix fragments ----------------
template <int KDIM, int MODE, bool HASBIAS>
__global__ void __launch_bounds__(256, 2)
gemm_bf16(const uint32_t* __restrict__ A, const uint32_t* __restrict__ Wpk,
          const float* __restrict__ bias, uint32_t* __restrict__ out, int ldo,
          int rows, const uint32_t* __restrict__ fbx, const int* __restrict__ fbmask)
{
    constexpr int K2  = KDIM / 2;
    constexpr int K2P = (KDIM == 160) ? 84 : 68;
    constexpr int KQ  = K2 / 4;

    extern __shared__ __align__(16) uint32_t dsm[];
    uint32_t* As = dsm;                  // [128][K2P]
    uint32_t* Bs = dsm + 128 * K2P;      // [128][K2P]

    int t = threadIdx.x, lane = t & 31, wid = t >> 5;
    int g = lane >> 2, tig = lane & 3;
    int wm = wid & 3, wn = wid >> 2;
    int row0 = blockIdx.x * 128;
    int colbase = blockIdx.y * 128;

#pragma unroll
    for (int it = 0; it < 128 * KQ / 256; it++) {
        int i = t + it * 256;
        int r = i / KQ, q = (i - r * KQ) * 4;
        int gr = row0 + r;
        uint4 v = make_uint4(0u, 0u, 0u, 0u);
        if (gr < rows) v = *reinterpret_cast<const uint4*>(&A[(size_t)gr * K2 + q]);
        *reinterpret_cast<uint4*>(&As[r * K2P + q]) = v;
    }
#pragma unroll
    for (int it = 0; it < 128 * KQ / 256; it++) {
        int i = t + it * 256;
        int c = i / KQ, q = (i - c * KQ) * 4;
        uint4 v = *reinterpret_cast<const uint4*>(&Wpk[(size_t)(colbase + c) * K2 + q]);
        *reinterpret_cast<uint4*>(&Bs[c * K2P + q]) = v;
    }
    __syncthreads();

    uint32_t aBase = smaddr(As) + ((wm * 32 + (lane & 15)) * K2P + ((lane >> 4) << 2)) * 4;
    uint32_t bBase = smaddr(Bs) + ((wn * 64 + (lane & 7)) * K2P + ((lane & 8) ? 4 : 0)) * 4;

    float acc[2][8][4];
#pragma unroll
    for (int i = 0; i < 2; i++)
#pragma unroll
        for (int j = 0; j < 8; j++)
#pragma unroll
            for (int k = 0; k < 4; k++) acc[i][j][k] = 0.f;

#pragma unroll
    for (int s = 0; s < K2 / 8; s++) {
        uint32_t a[2][4];
        ldsm_x4(a[0][0], a[0][1], a[0][2], a[0][3], aBase + s * 32);
        ldsm_x4(a[1][0], a[1][1], a[1][2], a[1][3], aBase + 16 * K2P * 4 + s * 32);
#pragma unroll
        for (int nt = 0; nt < 8; nt++) {
            uint32_t b0, b1;
            ldsm_x2(b0, b1, bBase + nt * 8 * K2P * 4 + s * 32);
            mma_bf16(acc[0][nt], a[0], b0, b1);
            mma_bf16(acc[1][nt], a[1], b0, b1);
        }
    }

#pragma unroll
    for (int mt = 0; mt < 2; mt++) {
#pragma unroll
        for (int half = 0; half < 2; half++) {
            int gr = row0 + wm * 32 + mt * 16 + g + half * 8;
            if (gr >= rows) continue;
            bool fb = false;
            if (MODE == 2) fb = (fbmask[gr] == 0);
#pragma unroll
            for (int nt = 0; nt < 8; nt++) {
                int col = colbase + wn * 64 + nt * 8 + tig * 2;
                int pair = wn * 32 + nt * 4 + tig;
                float v0 = acc[mt][nt][half * 2 + 0];
                float v1 = acc[mt][nt][half * 2 + 1];
                if (HASBIAS) { v0 += bias[col]; v1 += bias[col + 1]; }
                if (MODE == 2) {
                    if (fb) {
                        float2 f = unpk(fbx[(size_t)gr * 64 + pair]);
                        v0 = f.x; v1 = f.y;
                    }
                    v0 = fmaxf(v0, 0.f);
                    v1 = fmaxf(v1, 0.f);
                }
                out[(size_t)gr * ldo + (colbase >> 1) + pair] = packbf(v0, v1);
            }
        }
    }
}

// ---------------- local-context attention on packed bf16 qkv: one warp per node ----------------
__global__ void attn_kernel(const uint32_t* __restrict__ qkvb,
                            const int* __restrict__ nbr_idx,
                            const int* __restrict__ nbr_mask,
                            uint32_t* __restrict__ ob)
{
    int n = (blockIdx.x * blockDim.x + threadIdx.x) >> 5;
    if (n >= N_NODES) return;
    int lane = threadIdx.x & 31;
    int p2 = lane * 2;

    uint2 qp = *reinterpret_cast<const uint2*>(&qkvb[(size_t)n * 192 + p2]);
    float2 qa = unpk(qp.x), qb = unpk(qp.y);

    int nb = 0, mk = 0;
    if (lane < 16) {
        nb = nbr_idx[n * K_NBR + lane];
        mk = nbr_mask[n * K_NBR + lane];
    }
    unsigned mb = __ballot_sync(0xffffffffu, (lane < 16) && mk);

    int idxs[CTX];
    float sc[CTX];
#pragma unroll
    for (int c = 0; c < CTX; c++) {
        int id = (c == 0) ? n : __shfl_sync(0xffffffffu, nb, c - 1);
        idxs[c] = id;
        uint2 kp = *reinterpret_cast<const uint2*>(&qkvb[(size_t)id * 192 + 64 + p2]);
        float2 ka = unpk(kp.x), kb = unpk(kp.y);
        float s = qa.x * ka.x + qa.y * ka.y + qb.x * kb.x + qb.y * kb.y;
        s += __shfl_xor_sync(0xffffffffu, s, 4);
        s += __shfl_xor_sync(0xffffffffu, s, 2);
        s += __shfl_xor_sync(0xffffffffu, s, 1);
        s *= 0.17677669529663687f;
        if (c > 0 && !((mb >> (c - 1)) & 1)) s = -1e9f;
        sc[c] = s;
    }

    float mx = sc[0];
#pragma unroll
    for (int c = 1; c < CTX; c++) mx = fmaxf(mx, sc[c]);
    float den = 0.f;
#pragma unroll
    for (int c = 0; c < CTX; c++) { sc[c] = __expf(sc[c] - mx); den += sc[c]; }
    float inv = 1.f / den;

    float4 av = make_float4(0.f, 0.f, 0.f, 0.f);
#pragma unroll
    for (int c = 0; c < CTX; c++) {
        uint2 vp = *reinterpret_cast<const uint2*>(&qkvb[(size_t)idxs[c] * 192 + 128 + p2]);
        float2 va = unpk(vp.x), vb = unpk(vp.y);
        float p = sc[c];
        av.x += p * va.x; av.y += p * va.y; av.z += p * vb.x; av.w += p * vb.y;
    }
    ob[(size_t)n * 64 + p2]     = packbf(av.x * inv, av.y * inv);
    ob[(size_t)n * 64 + p2 + 1] = packbf(av.z * inv, av.w * inv);
}

// ---------------- fused edge MLP, tf32 TC phase 2: 64 edges per block ----------------
// smem: W2s[128][72] fp32(tf32) ; h1s[64][132] fp32(tf32) ; part[64][2]
__global__ void __launch_bounds__(256)
edge_fused_kernel(const uint32_t* __restrict__ uwb,
                  const int* __restrict__ edges,
                  const float* __restrict__ ef,
                  const float* __restrict__ eW1,
                  const float* __restrict__ eW2,    // fp32 [128][64]
                  const float* __restrict__ eb2,
                  const float* __restrict__ eW3,
                  const float* __restrict__ eb3,
                  float* __restrict__ out)
{
    extern __shared__ __align__(16) float edsm[];
    float* W2s = edsm;                    // [128][72]
    float* h1s = edsm + 128 * 72;         // [64][132]
    float* part = h1s + 64 * 132;         // [64][2]

    int t = threadIdx.x;
    int lane = t & 31, wid = t >> 5;
    int g = lane >> 2, tig = lane & 3;
    int e0 = blockIdx.x * 64;

    // stage W2 (tf32-rounded), k-major rows
#pragma unroll
    for (int it = 0; it < 8; it++) {
        int i = t + it * 256;               // 2048 float4
        int k = i >> 4, c4 = (i & 15) << 2;
        float4 v = *reinterpret_cast<const float4*>(&eW2[(size_t)k * 64 + c4]);
        W2s[k * 72 + c4 + 0] = to_tf32(v.x);
        W2s[k * 72 + c4 + 1] = to_tf32(v.y);
        W2s[k * 72 + c4 + 2] = to_tf32(v.z);
        W2s[k * 72 + c4 + 3] = to_tf32(v.w);
    }

    const float* wef0 = eW1 + 256 * 128;
    const float* wef1 = eW1 + 257 * 128;
    float4 we0 = *reinterpret_cast<const float4*>(&wef0[lane * 4]);
    float4 we1 = *reinterpret_cast<const float4*>(&wef1[lane * 4]);

    // phase 1: h1 (tf32-rounded fp32) for this warp's 8 edges
#pragma unroll
    for (int ee = 0; ee < 8; ee++) {
        int el = wid * 8 + ee;
        int e = e0 + el;
        int s = edges[2 * e], d = edges[2 * e + 1];
        float f0 = ef[2 * e], f1 = ef[2 * e + 1];
        uint2 up2 = *reinterpret_cast<const uint2*>(&uwb[(size_t)s * 128 + lane * 2]);
        uint2 wp2 = *reinterpret_cast<const uint2*>(&uwb[(size_t)d * 128 + 64 + lane * 2]);
        float2 ua = unpk(up2.x), ub = unpk(up2.y);
        float2 wa = unpk(wp2.x), wb = unpk(wp2.y);
        float4 h;
        h.x = to_tf32(fmaxf(ua.x + wa.x + f0 * we0.x + f1 * we1.x, 0.f));
        h.y = to_tf32(fmaxf(ua.y + wa.y + f0 * we0.y + f1 * we1.y, 0.f));
        h.z = to_tf32(fmaxf(ub.x + wb.x + f0 * we0.z + f1 * we1.z, 0.f));
        h.w = to_tf32(fmaxf(ub.y + wb.y + f0 * we0.w + f1 * we1.w, 0.f));
        *reinterpret_cast<float4*>(&h1s[el * 132 + lane * 4]) = h;
    }
    __syncthreads();

    // phase 2: h2 = h1 @ W2 via tf32 mma
    int rb = (wid & 3) * 16;
    int cb = (wid >> 2) * 32;

    float acc[4][4];
#pragma unroll
    for (int i = 0; i < 4; i++)
#pragma unroll
        for (int j = 0; j < 4; j++) acc[i][j] = 0.f;

#pragma unroll
    for (int kb = 0; kb < 128; kb += 8) {
        uint32_t a[4];
        a[0] = __float_as_uint(h1s[(rb + g) * 132 + kb + tig]);
        a[1] = __float_as_uint(h1s[(rb + g + 8) * 132 + kb + tig]);
        a[2] = __float_as_uint(h1s[(rb + g) * 132 + kb + tig + 4]);
        a[3] = __float_as_uint(h1s[(rb + g + 8) * 132 + kb + tig + 4]);
#pragma unroll
        for (int nt = 0; nt < 4; nt++) {
            int c = cb + nt * 8 + g;
            uint32_t b0 = __float_as_uint(W2s[(kb + tig) * 72 + c]);
            uint32_t b1 = __float_as_uint(W2s[(kb + tig + 4) * 72 + c]);
            mma_tf32(acc[nt], a, b0, b1);
        }
    }

    // logit partials: relu(h2 + b2) . W3
    float pg = 0.f, pg8 = 0.f;
#pragma unroll
    for (int nt = 0; nt < 4; nt++) {
        int col = cb + nt * 8 + tig * 2;
        float b20 = eb2[col], b21 = eb2[col + 1];
        float w30 = eW3[col], w31 = eW3[col + 1];
        pg  += fmaxf(acc[nt][0] + b20, 0.f) * w30 + fmaxf(acc[nt][1] + b21, 0.f) * w31;
        pg8 += fmaxf(acc[nt][2] + b20, 0.f) * w30 + fmaxf(acc[nt][3] + b21, 0.f) * w31;
    }
    pg  += __shfl_xor_sync(0xffffffffu, pg, 1);
    pg  += __shfl_xor_sync(0xffffffffu, pg, 2);
    pg8 += __shfl_xor_sync(0xffffffffu, pg8, 1);
    pg8 += __shfl_xor_sync(0xffffffffu, pg8, 2);
    if (tig == 0) {
        part[(rb + g) * 2 + (wid >> 2)]     = pg;
        part[(rb + 8 + g) * 2 + (wid >> 2)] = pg8;
    }
    __syncthreads();
    if (t < 64) out[e0 + t] = part[t * 2] + part[t * 2 + 1] + eb3[0];
}

// ---------------- launch ----------------
extern "C" void kernel_launch(void* const* d_in, const int* in_sizes, int n_in,
                              void* d_out, int out_size)
{
    (void)in_sizes; (void)n_in; (void)out_size;
    const int*   type_idx   = (const int*)d_in[0];
    const int*   cat_idx    = (const int*)d_in[1];
    const int*   nbr_idx    = (const int*)d_in[2];
    const int*   nbr_mask   = (const int*)d_in[3];
    const int*   edges      = (const int*)d_in[4];
    const float* log_deg    = (const float*)d_in[5];
    const float* edge_feats = (const float*)d_in[6];
    const float* type_embed = (const float*)d_in[7];
    const float* cat_embed0 = (const float*)d_in[8];
    const float* cat_embed1 = (const float*)d_in[9];
    const float* deg_W      = (const float*)d_in[10];
    const float* deg_b      = (const float*)d_in[11];
    const float* proj_W     = (const float*)d_in[12];
    const float* proj_b     = (const float*)d_in[13];
    const float* Wqkv       = (const float*)d_in[14];
    const float* bqkv       = (const float*)d_in[15];
    const float* Wo         = (const float*)d_in[16];
    const float* bo         = (const float*)d_in[17];
    const float* eW1        = (const float*)d_in[18];
    const float* eb1        = (const float*)d_in[19];
    const float* eW2        = (const float*)d_in[20];
    const float* eb2        = (const float*)d_in[21];
    const float* eW3        = (const float*)d_in[22];
    const float* eb3        = (const float*)d_in[23];
    float* out = (float*)d_out;

    uint32_t *featsb, *xab, *xbb, *qkvb, *ob, *uwb, *wpk;
    float* biasuw; int* has;
    cudaGetSymbolAddress((void**)&featsb, g_featsb);
    cudaGetSymbolAddress((void**)&xab, g_xab);
    cudaGetSymbolAddress((void**)&xbb, g_xbb);
    cudaGetSymbolAddress((void**)&qkvb, g_qkvb);
    cudaGetSymbolAddress((void**)&ob, g_ob);
    cudaGetSymbolAddress((void**)&uwb, g_uwb);
    cudaGetSymbolAddress((void**)&has, g_has);
    cudaGetSymbolAddress((void**)&wpk, g_wpk);
    cudaGetSymbolAddress((void**)&biasuw, g_biasuw);

    const int SM128 = 2 * 128 * 68 * 4;
    const int SM160 = 2 * 128 * 84 * 4;
    const int SMEDGE = (128 * 72 + 64 * 132 + 128) * 4;   // 71168
    cudaFuncSetAttribute(gemm_bf16<160, 0, true>, cudaFuncAttributeMaxDynamicSharedMemorySize, SM160);
    cudaFuncSetAttribute(gemm_bf16<128, 0, true>, cudaFuncAttributeMaxDynamicSharedMemorySize, SM128);
    cudaFuncSetAttribute(gemm_bf16<128, 2, true>, cudaFuncAttributeMaxDynamicSharedMemorySize, SM128);
    cudaFuncSetAttribute(edge_fused_kernel, cudaFuncAttributeMaxDynamicSharedMemorySize, SMEDGE);

    pack_all_kernel<<<(125184 + 255) / 256, 256>>>(proj_W, Wqkv, Wo, eW1, eb1, wpk, biasuw);
    encode_kernel<<<(N_NODES * 80 + N_NODES + 255) / 256, 256>>>(
        type_idx, cat_idx, log_deg, type_embed, cat_embed0, cat_embed1,
        deg_W, deg_b, nbr_mask, featsb, has);

    int gN = (N_NODES + 127) / 128;
    gemm_bf16<160, 0, true><<<gN, 256, SM160>>>(
        featsb, wpk + WPK_PROJ, proj_b, xab, 64, N_NODES, nullptr, nullptr);

    uint32_t* xcur = xab;
    uint32_t* xnxt = xbb;
    for (int l = 0; l < 3; l++) {
        gemm_bf16<128, 0, true><<<dim3(gN, 3), 256, SM128>>>(
            xcur, wpk + WPK_QKV + l * 24576, bqkv + (size_t)l * 384,
            qkvb, 192, N_NODES, nullptr, nullptr);
        attn_kernel<<<(N_NODES + 7) / 8, 256>>>(qkvb, nbr_idx, nbr_mask, ob);
        gemm_bf16<128, 2, true><<<gN, 256, SM128>>>(
            ob, wpk + WPK_WO + l * 8192, bo + (size_t)l * 128,
            xnxt, 64, N_NODES, xcur, has);
        uint32_t* tmp = xcur; xcur = xnxt; xnxt = tmp;
    }

    gemm_bf16<128, 0, true><<<dim3(gN, 2), 256, SM128>>>(
        xcur, wpk + WPK_UW, biasuw, uwb, 128, N_NODES, nullptr, nullptr);

    edge_fused_kernel<<<N_EDGES / 64, 256, SMEDGE>>>(
        uwb, edges, edge_feats, eW1, eW2, eb2, eW3, eb3, out);
}